// round 1
// baseline (speedup 1.0000x reference)
#include <cuda_runtime.h>
#include <cstdint>
#include <math.h>

#define MAXN 65536
#define MAXE (1 << 21)
#define DCOL 256

// ---------------- static device scratch ----------------
__device__ float g_hw[MAXN * DCOL];   // (h @ W) * dinv[row]
__device__ float g_h1[MAXN * DCOL];   // ping
__device__ float g_h2[MAXN * DCOL];   // pong
__device__ int   g_deg[MAXN];
__device__ int   g_scan[MAXN];
__device__ int   g_rowptr[MAXN + 1];
__device__ int   g_cursor[MAXN];
__device__ int   g_csr[MAXE];
__device__ int   g_bsums[128];
__device__ float g_dinv[MAXN];
__device__ float g_colsum[DCOL];
__device__ float g_colsq[DCOL];
__device__ float g_scale[DCOL];
__device__ float g_shift[DCOL];

// ---------------- preprocessing ----------------
__global__ void k_init_deg(int n) {
    int i = blockIdx.x * blockDim.x + threadIdx.x;
    if (i < n) g_deg[i] = 1;  // self loop
}

__global__ void k_count_deg(const int* __restrict__ dst, int e) {
    int i = blockIdx.x * blockDim.x + threadIdx.x;
    if (i < e) atomicAdd(&g_deg[dst[i]], 1);
}

__global__ void k_dinv(int n) {
    int i = blockIdx.x * blockDim.x + threadIdx.x;
    if (i < n) g_dinv[i] = rsqrtf((float)g_deg[i]);
}

__global__ void k_scan_block(int n) {
    __shared__ int sh[1024];
    int i = blockIdx.x * 1024 + threadIdx.x;
    int v = (i < n) ? g_deg[i] : 0;
    sh[threadIdx.x] = v;
    __syncthreads();
    for (int off = 1; off < 1024; off <<= 1) {
        int t = (threadIdx.x >= off) ? sh[threadIdx.x - off] : 0;
        __syncthreads();
        sh[threadIdx.x] += t;
        __syncthreads();
    }
    if (i < n) g_scan[i] = sh[threadIdx.x];
    if (threadIdx.x == 1023) g_bsums[blockIdx.x] = sh[1023];
}

__global__ void k_scan_sums(int nb) {
    if (threadIdx.x == 0 && blockIdx.x == 0) {
        int acc = 0;
        for (int i = 0; i < nb; i++) { acc += g_bsums[i]; g_bsums[i] = acc; }
    }
}

__global__ void k_scan_final(int n) {
    int i = blockIdx.x * 1024 + threadIdx.x;
    if (i < n) {
        int off = (blockIdx.x > 0) ? g_bsums[blockIdx.x - 1] : 0;
        int incl = g_scan[i] + off;
        g_rowptr[i + 1] = incl;
        g_cursor[i] = incl - g_deg[i];
        if (i == 0) g_rowptr[0] = 0;
    }
}

__global__ void k_fill_csr(const int* __restrict__ src, const int* __restrict__ dst, int e) {
    int i = blockIdx.x * blockDim.x + threadIdx.x;
    if (i < e) {
        int d = dst[i];
        int p = atomicAdd(&g_cursor[d], 1);
        g_csr[p] = src[i];
    }
}

__global__ void k_fill_self(int n) {
    int i = blockIdx.x * blockDim.x + threadIdx.x;
    if (i < n) {
        int p = atomicAdd(&g_cursor[i], 1);
        g_csr[p] = i;
    }
}

// ---------------- SGEMM: C[r][c] = (A @ W)[r][c] * dinv[r] ----------------
// M x 256 @ 256 x 256, BM=BN=128, BK=8, 256 threads, TM=TN=8
__global__ void k_sgemm_scale(const float* __restrict__ A, const float* __restrict__ W,
                              float* __restrict__ C, int M) {
    const int K = 256, NC = 256;
    __shared__ float As[8][128];
    __shared__ float Bs[8][128];
    int tid = threadIdx.x;
    int brow = blockIdx.x * 128;
    int bcol = blockIdx.y * 128;

    int aRow = tid >> 1;          // 0..127
    int aCol = (tid & 1) * 4;     // 0 or 4
    int bRow = tid >> 5;          // 0..7
    int bCol = (tid & 31) * 4;

    int tRow = (tid >> 4) * 8;
    int tCol = (tid & 15) * 8;

    float acc[8][8];
#pragma unroll
    for (int i = 0; i < 8; i++)
#pragma unroll
        for (int j = 0; j < 8; j++) acc[i][j] = 0.f;

    for (int kt = 0; kt < K; kt += 8) {
        float4 a4 = make_float4(0.f, 0.f, 0.f, 0.f);
        int gRow = brow + aRow;
        if (gRow < M) a4 = *(const float4*)(A + (size_t)gRow * K + kt + aCol);
        As[aCol + 0][aRow] = a4.x;
        As[aCol + 1][aRow] = a4.y;
        As[aCol + 2][aRow] = a4.z;
        As[aCol + 3][aRow] = a4.w;
        float4 b4 = *(const float4*)(W + (size_t)(kt + bRow) * NC + bcol + bCol);
        *(float4*)(&Bs[bRow][bCol]) = b4;
        __syncthreads();
#pragma unroll
        for (int k = 0; k < 8; ++k) {
            float ra[8], rb[8];
#pragma unroll
            for (int i = 0; i < 8; i++) ra[i] = As[k][tRow + i];
#pragma unroll
            for (int j = 0; j < 8; j++) rb[j] = Bs[k][tCol + j];
#pragma unroll
            for (int i = 0; i < 8; i++)
#pragma unroll
                for (int j = 0; j < 8; j++) acc[i][j] += ra[i] * rb[j];
        }
        __syncthreads();
    }
#pragma unroll
    for (int i = 0; i < 8; i++) {
        int r = brow + tRow + i;
        if (r < M) {
            float s = g_dinv[r];
#pragma unroll
            for (int j = 0; j < 8; j += 4) {
                float4 v;
                v.x = acc[i][j + 0] * s;
                v.y = acc[i][j + 1] * s;
                v.z = acc[i][j + 2] * s;
                v.w = acc[i][j + 3] * s;
                *(float4*)(C + (size_t)r * NC + bcol + tCol + j) = v;
            }
        }
    }
}

// ---------------- aggregation: z[d][t] = prev[d][t] + dinv[d]*sum_s hws[s][t] + b[t] ----------------
__global__ void k_agg(const float* __restrict__ hws, const float* __restrict__ prev,
                      const float* __restrict__ bias, float* __restrict__ z, int n) {
    int row = blockIdx.x;
    if (row >= n) return;
    int t = threadIdx.x;
    int s0 = g_rowptr[row], s1 = g_rowptr[row + 1];
    float acc = 0.f;
    for (int e = s0; e < s1; ++e) {
        int s = g_csr[e];
        acc += hws[(size_t)s * DCOL + t];
    }
    float val = g_dinv[row] * acc + bias[t];
    if (prev) val += prev[(size_t)row * DCOL + t];
    z[(size_t)row * DCOL + t] = val;
}

// ---------------- batchnorm ----------------
__global__ void k_zero_stats() {
    int t = threadIdx.x;
    g_colsum[t] = 0.f;
    g_colsq[t] = 0.f;
}

__global__ void k_stats(const float* __restrict__ z, int n) {
    int t = threadIdx.x;
    int r0 = blockIdx.x * 128;
    int r1 = min(n, r0 + 128);
    float s = 0.f, q = 0.f;
    for (int r = r0; r < r1; ++r) {
        float v = z[(size_t)r * DCOL + t];
        s += v;
        q += v * v;
    }
    atomicAdd(&g_colsum[t], s);
    atomicAdd(&g_colsq[t], q);
}

__global__ void k_bn_finalize(const float* __restrict__ gamma, const float* __restrict__ beta, int n) {
    int t = threadIdx.x;
    float inv_n = 1.f / (float)n;
    float mu = g_colsum[t] * inv_n;
    float var = g_colsq[t] * inv_n - mu * mu;
    float rs = rsqrtf(var + 1e-5f);
    float sc = gamma[t] * rs;
    g_scale[t] = sc;
    g_shift[t] = beta[t] - mu * sc;
}

__global__ void k_apply(float* __restrict__ h, int total) {
    int i = blockIdx.x * blockDim.x + threadIdx.x;
    if (i < total) {
        int t = i & (DCOL - 1);
        float v = h[i] * g_scale[t] + g_shift[t];
        h[i] = v > 0.f ? v : expm1f(v);
    }
}

// ---------------- pool + readout ----------------
__global__ void k_pool_out(const float* __restrict__ h, const int* __restrict__ batch,
                           const float* __restrict__ Wr, const float* __restrict__ br,
                           float* __restrict__ out, int n) {
    int g = blockIdx.x;
    int t = threadIdx.x;
    // lower_bound(batch, g)
    int lo = 0, hi = n;
    while (lo < hi) { int m = (lo + hi) >> 1; if (batch[m] < g) lo = m + 1; else hi = m; }
    int start = lo;
    lo = start; hi = n;
    while (lo < hi) { int m = (lo + hi) >> 1; if (batch[m] < g + 1) lo = m + 1; else hi = m; }
    int end = lo;

    float sum = 0.f;
    for (int r = start; r < end; ++r) sum += h[(size_t)r * DCOL + t];
    float cnt = (float)(end - start);
    float v = sum / fmaxf(cnt, 1.f);

    __shared__ float red[DCOL];
    for (int c = 0; c < 2; ++c) {
        red[t] = v * Wr[t * 2 + c];
        __syncthreads();
        for (int s = 128; s > 0; s >>= 1) {
            if (t < s) red[t] += red[t + s];
            __syncthreads();
        }
        if (t == 0) out[g * 2 + c] = red[0] + br[c];
        __syncthreads();
    }
}

// ---------------- launch ----------------
extern "C" void kernel_launch(void* const* d_in, const int* in_sizes, int n_in,
                              void* d_out, int out_size) {
    const float* x     = (const float*)d_in[0];
    const int*   ei    = (const int*)d_in[1];
    const int*   batch = (const int*)d_in[2];
    const float* W[3]     = { (const float*)d_in[3],  (const float*)d_in[7],  (const float*)d_in[11] };
    const float* b[3]     = { (const float*)d_in[4],  (const float*)d_in[8],  (const float*)d_in[12] };
    const float* gamma[3] = { (const float*)d_in[5],  (const float*)d_in[9],  (const float*)d_in[13] };
    const float* beta[3]  = { (const float*)d_in[6],  (const float*)d_in[10], (const float*)d_in[14] };
    const float* Wr = (const float*)d_in[15];
    const float* br = (const float*)d_in[16];
    float* out = (float*)d_out;

    int n = in_sizes[0] / DCOL;
    int e = in_sizes[1] / 2;
    int g = out_size / 2;
    const int* src = ei;
    const int* dst = ei + e;

    float *p_hw, *p_h1, *p_h2;
    cudaGetSymbolAddress((void**)&p_hw, g_hw);
    cudaGetSymbolAddress((void**)&p_h1, g_h1);
    cudaGetSymbolAddress((void**)&p_h2, g_h2);

    // ---- preprocessing: degree, dinv, CSR ----
    int nb256_n = (n + 255) / 256;
    int nb256_e = (e + 255) / 256;
    int nb1024  = (n + 1023) / 1024;

    k_init_deg<<<nb256_n, 256>>>(n);
    k_count_deg<<<nb256_e, 256>>>(dst, e);
    k_dinv<<<nb256_n, 256>>>(n);
    k_scan_block<<<nb1024, 1024>>>(n);
    k_scan_sums<<<1, 32>>>(nb1024);
    k_scan_final<<<nb1024, 1024>>>(n);
    k_fill_csr<<<nb256_e, 256>>>(src, dst, e);
    k_fill_self<<<nb256_n, 256>>>(n);

    dim3 gemm_grid((n + 127) / 128, 2);
    int total = n * DCOL;
    int nb_apply = (total + 255) / 256;
    int nb_stats = (n + 127) / 128;

    // ---- layer 0: h=x, prev=0 -> g_h1 ----
    k_sgemm_scale<<<gemm_grid, 256>>>(x, W[0], p_hw, n);
    k_agg<<<n, 256>>>(p_hw, nullptr, b[0], p_h1, n);
    k_zero_stats<<<1, 256>>>();
    k_stats<<<nb_stats, 256>>>(p_h1, n);
    k_bn_finalize<<<1, 256>>>(gamma[0], beta[0], n);
    k_apply<<<nb_apply, 256>>>(p_h1, total);

    // ---- layer 1: h=g_h1, prev=x -> g_h2 ----
    k_sgemm_scale<<<gemm_grid, 256>>>(p_h1, W[1], p_hw, n);
    k_agg<<<n, 256>>>(p_hw, x, b[1], p_h2, n);
    k_zero_stats<<<1, 256>>>();
    k_stats<<<nb_stats, 256>>>(p_h2, n);
    k_bn_finalize<<<1, 256>>>(gamma[1], beta[1], n);
    k_apply<<<nb_apply, 256>>>(p_h2, total);

    // ---- layer 2: h=g_h2, prev=g_h1 -> g_h1 (in-place add is elementwise-safe) ----
    k_sgemm_scale<<<gemm_grid, 256>>>(p_h2, W[2], p_hw, n);
    k_agg<<<n, 256>>>(p_hw, p_h1, b[2], p_h1, n);
    k_zero_stats<<<1, 256>>>();
    k_stats<<<nb_stats, 256>>>(p_h1, n);
    k_bn_finalize<<<1, 256>>>(gamma[2], beta[2], n);
    k_apply<<<nb_apply, 256>>>(p_h1, total);

    // ---- pool + readout ----
    k_pool_out<<<g, 256>>>(p_h1, batch, Wr, br, out, n);
}

// round 2
// speedup vs baseline: 1.2893x; 1.2893x over previous
#include <cuda_runtime.h>
#include <cstdint>
#include <math.h>

#define MAXN 65536
#define MAXE (1 << 21)
#define DCOL 256

// ---------------- static device scratch ----------------
__device__ float g_hw[MAXN * DCOL];   // (h @ W) * dinv[row]
__device__ float g_h1[MAXN * DCOL];   // z0 / z2
__device__ float g_h2[MAXN * DCOL];   // z1
__device__ int   g_deg[MAXN];
__device__ int   g_scan[MAXN];
__device__ int   g_rowptr[MAXN + 1];
__device__ int   g_cursor[MAXN];
__device__ int   g_csr[MAXE];
__device__ int   g_bsums[128];
__device__ float g_dinv[MAXN];
__device__ float g_colsum[DCOL];
__device__ float g_colsq[DCOL];
__device__ float g_sc[3][DCOL];   // per-layer BN scale
__device__ float g_sh[3][DCOL];   // per-layer BN shift

__device__ __forceinline__ float elu_act(float z, float sc, float sh) {
    float v = fmaf(z, sc, sh);
    return v > 0.f ? v : expm1f(v);
}

__device__ __forceinline__ uint32_t f2tf32(float x) {
    uint32_t r;
    asm("cvt.rna.tf32.f32 %0, %1;" : "=r"(r) : "f"(x));
    return r;
}

__device__ __forceinline__ void mma_tf32(float* d, const uint32_t* a, const uint32_t* b) {
    asm volatile(
        "mma.sync.aligned.m16n8k8.row.col.f32.tf32.tf32.f32 "
        "{%0,%1,%2,%3},{%4,%5,%6,%7},{%8,%9},{%0,%1,%2,%3};"
        : "+f"(d[0]), "+f"(d[1]), "+f"(d[2]), "+f"(d[3])
        : "r"(a[0]), "r"(a[1]), "r"(a[2]), "r"(a[3]), "r"(b[0]), "r"(b[1]));
}

// ---------------- preprocessing ----------------
__global__ void k_init_deg(int n) {
    int i = blockIdx.x * blockDim.x + threadIdx.x;
    if (i < n) g_deg[i] = 1;  // self loop
    if (blockIdx.x == 0 && threadIdx.x < DCOL) {
        g_colsum[threadIdx.x] = 0.f;
        g_colsq[threadIdx.x] = 0.f;
    }
}

__global__ void k_count_deg(const int* __restrict__ dst, int e) {
    int i = blockIdx.x * blockDim.x + threadIdx.x;
    if (i < e) atomicAdd(&g_deg[dst[i]], 1);
}

__global__ void k_dinv(int n) {
    int i = blockIdx.x * blockDim.x + threadIdx.x;
    if (i < n) g_dinv[i] = rsqrtf((float)g_deg[i]);
}

__global__ void k_scan_block(int n) {
    __shared__ int sh[1024];
    int i = blockIdx.x * 1024 + threadIdx.x;
    int v = (i < n) ? g_deg[i] : 0;
    sh[threadIdx.x] = v;
    __syncthreads();
    for (int off = 1; off < 1024; off <<= 1) {
        int t = (threadIdx.x >= off) ? sh[threadIdx.x - off] : 0;
        __syncthreads();
        sh[threadIdx.x] += t;
        __syncthreads();
    }
    if (i < n) g_scan[i] = sh[threadIdx.x];
    if (threadIdx.x == 1023) g_bsums[blockIdx.x] = sh[1023];
}

__global__ void k_scan_sums(int nb) {
    if (threadIdx.x == 0 && blockIdx.x == 0) {
        int acc = 0;
        for (int i = 0; i < nb; i++) { acc += g_bsums[i]; g_bsums[i] = acc; }
    }
}

__global__ void k_scan_final(int n) {
    int i = blockIdx.x * 1024 + threadIdx.x;
    if (i < n) {
        int off = (blockIdx.x > 0) ? g_bsums[blockIdx.x - 1] : 0;
        int incl = g_scan[i] + off;
        g_rowptr[i + 1] = incl;
        g_cursor[i] = incl - g_deg[i];
        if (i == 0) g_rowptr[0] = 0;
    }
}

__global__ void k_fill_csr(const int* __restrict__ src, const int* __restrict__ dst, int e) {
    int i = blockIdx.x * blockDim.x + threadIdx.x;
    if (i < e) {
        int d = dst[i];
        int p = atomicAdd(&g_cursor[d], 1);
        g_csr[p] = src[i];
    }
}

__global__ void k_fill_self(int n) {
    int i = blockIdx.x * blockDim.x + threadIdx.x;
    if (i < n) {
        int p = atomicAdd(&g_cursor[i], 1);
        g_csr[p] = i;
    }
}

// ---------------- TF32x3 tensor-core GEMM ----------------
// C[r][c] = (act(A) @ W)[r][c] * dinv[r], A: Mx256 fp32, W: 256x256.
// act applied if scl != nullptr: a = elu(a*scl[k] + sft[k]) (k = feature col of A).
// BM=BN=128, BK=16, 256 threads, 8 warps in 4(m) x 2(n), warp tile 32x64.
__global__ __launch_bounds__(256, 2)
void k_gemm(const float* __restrict__ A, const float* __restrict__ W,
            float* __restrict__ C, int M,
            const float* __restrict__ scl, const float* __restrict__ sft) {
    __shared__ float As_hi[128][17];
    __shared__ float As_lo[128][17];
    __shared__ float Bs_hi[16][132];
    __shared__ float Bs_lo[16][132];

    int tid = threadIdx.x;
    int brow = blockIdx.x * 128;
    int bcol = blockIdx.y * 128;

    int lane = tid & 31;
    int warp = tid >> 5;
    int wm = warp & 3;        // 0..3 -> rows wm*32
    int wn = warp >> 2;       // 0..1 -> cols wn*64
    int g  = lane >> 2;       // groupID 0..7
    int tg = lane & 3;        // thread-in-group 0..3

    // A load mapping: row = tid>>1, two float4 at cols (tid&1)*8 + {0,4}
    int aRow = tid >> 1;
    int aC   = (tid & 1) * 8;
    // B load mapping: row = tid>>4 (0..15), two float4 at cols (tid&15)*8 + {0,4}
    int bRow = tid >> 4;
    int bC   = (tid & 15) * 8;

    float acc[2][8][4];
#pragma unroll
    for (int mt = 0; mt < 2; mt++)
#pragma unroll
        for (int nt = 0; nt < 8; nt++)
#pragma unroll
            for (int j = 0; j < 4; j++) acc[mt][nt][j] = 0.f;

    for (int kt = 0; kt < 256; kt += 16) {
        // --- load A tile (with optional lazy activation) ---
        {
            int gr = brow + aRow;
#pragma unroll
            for (int h = 0; h < 2; h++) {
                int c0 = aC + h * 4;
                float4 v = make_float4(0.f, 0.f, 0.f, 0.f);
                if (gr < M) v = *(const float4*)(A + (size_t)gr * 256 + kt + c0);
                if (scl) {
                    v.x = elu_act(v.x, scl[kt + c0 + 0], sft[kt + c0 + 0]);
                    v.y = elu_act(v.y, scl[kt + c0 + 1], sft[kt + c0 + 1]);
                    v.z = elu_act(v.z, scl[kt + c0 + 2], sft[kt + c0 + 2]);
                    v.w = elu_act(v.w, scl[kt + c0 + 3], sft[kt + c0 + 3]);
                }
                float hx = __uint_as_float(f2tf32(v.x));
                float hy = __uint_as_float(f2tf32(v.y));
                float hz = __uint_as_float(f2tf32(v.z));
                float hw = __uint_as_float(f2tf32(v.w));
                As_hi[aRow][c0 + 0] = hx;
                As_hi[aRow][c0 + 1] = hy;
                As_hi[aRow][c0 + 2] = hz;
                As_hi[aRow][c0 + 3] = hw;
                As_lo[aRow][c0 + 0] = __uint_as_float(f2tf32(v.x - hx));
                As_lo[aRow][c0 + 1] = __uint_as_float(f2tf32(v.y - hy));
                As_lo[aRow][c0 + 2] = __uint_as_float(f2tf32(v.z - hz));
                As_lo[aRow][c0 + 3] = __uint_as_float(f2tf32(v.w - hw));
            }
        }
        // --- load B tile ---
        {
#pragma unroll
            for (int h = 0; h < 2; h++) {
                int c0 = bC + h * 4;
                float4 v = *(const float4*)(W + (size_t)(kt + bRow) * 256 + bcol + c0);
                float hx = __uint_as_float(f2tf32(v.x));
                float hy = __uint_as_float(f2tf32(v.y));
                float hz = __uint_as_float(f2tf32(v.z));
                float hw = __uint_as_float(f2tf32(v.w));
                Bs_hi[bRow][c0 + 0] = hx;
                Bs_hi[bRow][c0 + 1] = hy;
                Bs_hi[bRow][c0 + 2] = hz;
                Bs_hi[bRow][c0 + 3] = hw;
                Bs_lo[bRow][c0 + 0] = __uint_as_float(f2tf32(v.x - hx));
                Bs_lo[bRow][c0 + 1] = __uint_as_float(f2tf32(v.y - hy));
                Bs_lo[bRow][c0 + 2] = __uint_as_float(f2tf32(v.z - hz));
                Bs_lo[bRow][c0 + 3] = __uint_as_float(f2tf32(v.w - hw));
            }
        }
        __syncthreads();

#pragma unroll
        for (int ks = 0; ks < 2; ks++) {
            int k0 = ks * 8;
            uint32_t ah[2][4], al[2][4];
#pragma unroll
            for (int mt = 0; mt < 2; mt++) {
                int m = wm * 32 + mt * 16;
                ah[mt][0] = __float_as_uint(As_hi[m + g][k0 + tg]);
                ah[mt][1] = __float_as_uint(As_hi[m + g + 8][k0 + tg]);
                ah[mt][2] = __float_as_uint(As_hi[m + g][k0 + tg + 4]);
                ah[mt][3] = __float_as_uint(As_hi[m + g + 8][k0 + tg + 4]);
                al[mt][0] = __float_as_uint(As_lo[m + g][k0 + tg]);
                al[mt][1] = __float_as_uint(As_lo[m + g + 8][k0 + tg]);
                al[mt][2] = __float_as_uint(As_lo[m + g][k0 + tg + 4]);
                al[mt][3] = __float_as_uint(As_lo[m + g + 8][k0 + tg + 4]);
            }
#pragma unroll
            for (int nt = 0; nt < 8; nt++) {
                int nn = wn * 64 + nt * 8 + g;
                uint32_t bh[2], bl[2];
                bh[0] = __float_as_uint(Bs_hi[k0 + tg][nn]);
                bh[1] = __float_as_uint(Bs_hi[k0 + tg + 4][nn]);
                bl[0] = __float_as_uint(Bs_lo[k0 + tg][nn]);
                bl[1] = __float_as_uint(Bs_lo[k0 + tg + 4][nn]);
#pragma unroll
                for (int mt = 0; mt < 2; mt++) {
                    mma_tf32(acc[mt][nt], ah[mt], bh);
                    mma_tf32(acc[mt][nt], ah[mt], bl);
                    mma_tf32(acc[mt][nt], al[mt], bh);
                }
            }
        }
        __syncthreads();
    }

    // epilogue: scale by dinv[r], write
#pragma unroll
    for (int mt = 0; mt < 2; mt++) {
        int r0 = brow + wm * 32 + mt * 16 + g;
        int r1 = r0 + 8;
        float s0 = (r0 < M) ? g_dinv[r0] : 0.f;
        float s1 = (r1 < M) ? g_dinv[r1] : 0.f;
#pragma unroll
        for (int nt = 0; nt < 8; nt++) {
            int col = bcol + wn * 64 + nt * 8 + tg * 2;
            if (r0 < M) {
                float2 v = make_float2(acc[mt][nt][0] * s0, acc[mt][nt][1] * s0);
                *(float2*)(C + (size_t)r0 * 256 + col) = v;
            }
            if (r1 < M) {
                float2 v = make_float2(acc[mt][nt][2] * s1, acc[mt][nt][3] * s1);
                *(float2*)(C + (size_t)r1 * 256 + col) = v;
            }
        }
    }
}

// ---------------- aggregation ----------------
// z[d] = act_or_raw(prev[d]) + dinv[d]*sum_s hws[s] + bias
// 4 rows per block, 64 lanes (float4) per row.
__global__ void k_agg(const float4* __restrict__ hws, const float* __restrict__ prev,
                      const float* __restrict__ pscl, const float* __restrict__ psft,
                      const float4* __restrict__ bias, float4* __restrict__ z, int n) {
    int row = blockIdx.x * 4 + (threadIdx.x >> 6);
    if (row >= n) return;
    int lane = threadIdx.x & 63;
    int s0 = g_rowptr[row], s1 = g_rowptr[row + 1];

    float4 acc = make_float4(0.f, 0.f, 0.f, 0.f);
    float4 acc2 = make_float4(0.f, 0.f, 0.f, 0.f);
    int e = s0;
    for (; e + 1 < s1; e += 2) {
        int sa = g_csr[e];
        int sb = g_csr[e + 1];
        float4 va = hws[(size_t)sa * 64 + lane];
        float4 vb = hws[(size_t)sb * 64 + lane];
        acc.x += va.x; acc.y += va.y; acc.z += va.z; acc.w += va.w;
        acc2.x += vb.x; acc2.y += vb.y; acc2.z += vb.z; acc2.w += vb.w;
    }
    if (e < s1) {
        int sa = g_csr[e];
        float4 va = hws[(size_t)sa * 64 + lane];
        acc.x += va.x; acc.y += va.y; acc.z += va.z; acc.w += va.w;
    }
    acc.x += acc2.x; acc.y += acc2.y; acc.z += acc2.z; acc.w += acc2.w;

    float d = g_dinv[row];
    float4 b = bias[lane];
    float4 o;
    o.x = fmaf(d, acc.x, b.x);
    o.y = fmaf(d, acc.y, b.y);
    o.z = fmaf(d, acc.z, b.z);
    o.w = fmaf(d, acc.w, b.w);
    if (prev) {
        const float4* p4 = (const float4*)prev;
        float4 p = p4[(size_t)row * 64 + lane];
        if (pscl) {
            int c = lane * 4;
            o.x += elu_act(p.x, pscl[c + 0], psft[c + 0]);
            o.y += elu_act(p.y, pscl[c + 1], psft[c + 1]);
            o.z += elu_act(p.z, pscl[c + 2], psft[c + 2]);
            o.w += elu_act(p.w, pscl[c + 3], psft[c + 3]);
        } else {
            o.x += p.x; o.y += p.y; o.z += p.z; o.w += p.w;
        }
    }
    z[(size_t)row * 64 + lane] = o;
}

// ---------------- batchnorm stats ----------------
__global__ void k_stats(const float* __restrict__ z, int n) {
    int t = threadIdx.x;
    int r0 = blockIdx.x * 128;
    int r1 = min(n, r0 + 128);
    float s = 0.f, q = 0.f;
    for (int r = r0; r < r1; ++r) {
        float v = z[(size_t)r * DCOL + t];
        s += v;
        q += v * v;
    }
    atomicAdd(&g_colsum[t], s);
    atomicAdd(&g_colsq[t], q);
}

__global__ void k_bn_finalize(const float* __restrict__ gamma, const float* __restrict__ beta,
                              int n, int layer) {
    int t = threadIdx.x;
    float inv_n = 1.f / (float)n;
    float mu = g_colsum[t] * inv_n;
    float var = g_colsq[t] * inv_n - mu * mu;
    float rs = rsqrtf(var + 1e-5f);
    float sc = gamma[t] * rs;
    g_sc[layer][t] = sc;
    g_sh[layer][t] = beta[t] - mu * sc;
    g_colsum[t] = 0.f;   // ready for next layer
    g_colsq[t] = 0.f;
}

// ---------------- pool + readout (lazy act on z2) ----------------
__global__ void k_pool_out(const float* __restrict__ z, const int* __restrict__ batch,
                           const float* __restrict__ Wr, const float* __restrict__ br,
                           float* __restrict__ out, int n) {
    int gg = blockIdx.x;
    int t = threadIdx.x;
    int lo = 0, hi = n;
    while (lo < hi) { int m = (lo + hi) >> 1; if (batch[m] < gg) lo = m + 1; else hi = m; }
    int start = lo;
    lo = start; hi = n;
    while (lo < hi) { int m = (lo + hi) >> 1; if (batch[m] < gg + 1) lo = m + 1; else hi = m; }
    int end = lo;

    float sc = g_sc[2][t], sh = g_sh[2][t];
    float sum = 0.f;
    for (int r = start; r < end; ++r)
        sum += elu_act(z[(size_t)r * DCOL + t], sc, sh);
    float cnt = (float)(end - start);
    float v = sum / fmaxf(cnt, 1.f);

    __shared__ float red[DCOL];
    for (int c = 0; c < 2; ++c) {
        red[t] = v * Wr[t * 2 + c];
        __syncthreads();
        for (int s = 128; s > 0; s >>= 1) {
            if (t < s) red[t] += red[t + s];
            __syncthreads();
        }
        if (t == 0) out[gg * 2 + c] = red[0] + br[c];
        __syncthreads();
    }
}

// ---------------- launch ----------------
extern "C" void kernel_launch(void* const* d_in, const int* in_sizes, int n_in,
                              void* d_out, int out_size) {
    const float* x     = (const float*)d_in[0];
    const int*   ei    = (const int*)d_in[1];
    const int*   batch = (const int*)d_in[2];
    const float* W[3]     = { (const float*)d_in[3],  (const float*)d_in[7],  (const float*)d_in[11] };
    const float* b[3]     = { (const float*)d_in[4],  (const float*)d_in[8],  (const float*)d_in[12] };
    const float* gamma[3] = { (const float*)d_in[5],  (const float*)d_in[9],  (const float*)d_in[13] };
    const float* beta[3]  = { (const float*)d_in[6],  (const float*)d_in[10], (const float*)d_in[14] };
    const float* Wr = (const float*)d_in[15];
    const float* br = (const float*)d_in[16];
    float* out = (float*)d_out;

    int n = in_sizes[0] / DCOL;
    int e = in_sizes[1] / 2;
    int g = out_size / 2;
    const int* src = ei;
    const int* dst = ei + e;

    float *p_hw, *p_z0, *p_z1, *p_sc, *p_sh;
    cudaGetSymbolAddress((void**)&p_hw, g_hw);
    cudaGetSymbolAddress((void**)&p_z0, g_h1);
    cudaGetSymbolAddress((void**)&p_z1, g_h2);
    cudaGetSymbolAddress((void**)&p_sc, g_sc);
    cudaGetSymbolAddress((void**)&p_sh, g_sh);

    // ---- preprocessing ----
    int nb256_n = (n + 255) / 256;
    int nb256_e = (e + 255) / 256;
    int nb1024  = (n + 1023) / 1024;

    k_init_deg<<<nb256_n, 256>>>(n);
    k_count_deg<<<nb256_e, 256>>>(dst, e);
    k_dinv<<<nb256_n, 256>>>(n);
    k_scan_block<<<nb1024, 1024>>>(n);
    k_scan_sums<<<1, 32>>>(nb1024);
    k_scan_final<<<nb1024, 1024>>>(n);
    k_fill_csr<<<nb256_e, 256>>>(src, dst, e);
    k_fill_self<<<nb256_n, 256>>>(n);

    dim3 gemm_grid((n + 127) / 128, 2);
    int nb_agg   = (n + 3) / 4;
    int nb_stats = (n + 127) / 128;

    // ---- layer 0: A=x raw, prev=none -> z0 ----
    k_gemm<<<gemm_grid, 256>>>(x, W[0], p_hw, n, nullptr, nullptr);
    k_agg<<<nb_agg, 256>>>((const float4*)p_hw, nullptr, nullptr, nullptr,
                           (const float4*)b[0], (float4*)p_z0, n);
    k_stats<<<nb_stats, 256>>>(p_z0, n);
    k_bn_finalize<<<1, 256>>>(gamma[0], beta[0], n, 0);

    // ---- layer 1: A=act0(z0), prev=x raw -> z1 ----
    k_gemm<<<gemm_grid, 256>>>(p_z0, W[1], p_hw, n, p_sc + 0 * DCOL, p_sh + 0 * DCOL);
    k_agg<<<nb_agg, 256>>>((const float4*)p_hw, x, nullptr, nullptr,
                           (const float4*)b[1], (float4*)p_z1, n);
    k_stats<<<nb_stats, 256>>>(p_z1, n);
    k_bn_finalize<<<1, 256>>>(gamma[1], beta[1], n, 1);

    // ---- layer 2: A=act1(z1), prev=act0(z0) -> z2 (overwrites z0, elementwise safe) ----
    k_gemm<<<gemm_grid, 256>>>(p_z1, W[2], p_hw, n, p_sc + 1 * DCOL, p_sh + 1 * DCOL);
    k_agg<<<nb_agg, 256>>>((const float4*)p_hw, p_z0, p_sc + 0 * DCOL, p_sh + 0 * DCOL,
                           (const float4*)b[2], (float4*)p_z0, n);
    k_stats<<<nb_stats, 256>>>(p_z0, n);
    k_bn_finalize<<<1, 256>>>(gamma[2], beta[2], n, 2);

    // ---- pool + readout (act2 lazy) ----
    k_pool_out<<<g, 256>>>(p_z0, batch, Wr, br, out, n);
}

// round 3
// speedup vs baseline: 1.2924x; 1.0024x over previous
#include <cuda_runtime.h>
#include <cstdint>
#include <math.h>

#define MAXN 65536
#define MAXE (1 << 21)
#define DCOL 256

// ---------------- static device scratch ----------------
__device__ float g_hw[MAXN * DCOL];   // (h @ W) * dinv[row]
__device__ float g_h1[MAXN * DCOL];   // z0 / z2
__device__ float g_h2[MAXN * DCOL];   // z1
__device__ int   g_deg[MAXN];
__device__ int   g_scan[MAXN];
__device__ int   g_rowptr[MAXN + 1];
__device__ int   g_cursor[MAXN];
__device__ int   g_csr[MAXE];
__device__ int   g_bsums[128];
__device__ float g_dinv[MAXN];
__device__ float g_colsum[DCOL];
__device__ float g_colsq[DCOL];
__device__ float g_sc[3][DCOL];   // per-layer BN scale
__device__ float g_sh[3][DCOL];   // per-layer BN shift

__device__ __forceinline__ float elu_act(float z, float sc, float sh) {
    float v = fmaf(z, sc, sh);
    return v > 0.f ? v : expm1f(v);
}

__device__ __forceinline__ uint32_t f2tf32(float x) {
    uint32_t r;
    asm("cvt.rna.tf32.f32 %0, %1;" : "=r"(r) : "f"(x));
    return r;
}

__device__ __forceinline__ void mma_tf32(float* d, const uint32_t* a, const uint32_t* b) {
    asm volatile(
        "mma.sync.aligned.m16n8k8.row.col.f32.tf32.tf32.f32 "
        "{%0,%1,%2,%3},{%4,%5,%6,%7},{%8,%9},{%0,%1,%2,%3};"
        : "+f"(d[0]), "+f"(d[1]), "+f"(d[2]), "+f"(d[3])
        : "r"(a[0]), "r"(a[1]), "r"(a[2]), "r"(a[3]), "r"(b[0]), "r"(b[1]));
}

// ---------------- preprocessing ----------------
__global__ void k_init_deg(int n) {
    int i = blockIdx.x * blockDim.x + threadIdx.x;
    if (i < n) g_deg[i] = 1;  // self loop
    if (blockIdx.x == 0 && threadIdx.x < DCOL) {
        g_colsum[threadIdx.x] = 0.f;
        g_colsq[threadIdx.x] = 0.f;
    }
}

__global__ void k_count_deg(const int* __restrict__ dst, int e) {
    int i = blockIdx.x * blockDim.x + threadIdx.x;
    if (i < e) atomicAdd(&g_deg[dst[i]], 1);
}

__global__ void k_dinv(int n) {
    int i = blockIdx.x * blockDim.x + threadIdx.x;
    if (i < n) g_dinv[i] = rsqrtf((float)g_deg[i]);
}

__global__ void k_scan_block(int n) {
    __shared__ int sh[1024];
    int i = blockIdx.x * 1024 + threadIdx.x;
    int v = (i < n) ? g_deg[i] : 0;
    sh[threadIdx.x] = v;
    __syncthreads();
    for (int off = 1; off < 1024; off <<= 1) {
        int t = (threadIdx.x >= off) ? sh[threadIdx.x - off] : 0;
        __syncthreads();
        sh[threadIdx.x] += t;
        __syncthreads();
    }
    if (i < n) g_scan[i] = sh[threadIdx.x];
    if (threadIdx.x == 1023) g_bsums[blockIdx.x] = sh[1023];
}

__global__ void k_scan_sums(int nb) {
    if (threadIdx.x == 0 && blockIdx.x == 0) {
        int acc = 0;
        for (int i = 0; i < nb; i++) { acc += g_bsums[i]; g_bsums[i] = acc; }
    }
}

__global__ void k_scan_final(int n) {
    int i = blockIdx.x * 1024 + threadIdx.x;
    if (i < n) {
        int off = (blockIdx.x > 0) ? g_bsums[blockIdx.x - 1] : 0;
        int incl = g_scan[i] + off;
        g_rowptr[i + 1] = incl;
        g_cursor[i] = incl - g_deg[i];
        if (i == 0) g_rowptr[0] = 0;
    }
}

__global__ void k_fill_csr(const int* __restrict__ src, const int* __restrict__ dst, int e) {
    int i = blockIdx.x * blockDim.x + threadIdx.x;
    if (i < e) {
        int d = dst[i];
        int p = atomicAdd(&g_cursor[d], 1);
        g_csr[p] = src[i];
    }
}

__global__ void k_fill_self(int n) {
    int i = blockIdx.x * blockDim.x + threadIdx.x;
    if (i < n) {
        int p = atomicAdd(&g_cursor[i], 1);
        g_csr[p] = i;
    }
}

// ---------------- TF32x3 tensor-core GEMM ----------------
// C[r][c] = (act(A) @ W)[r][c] * dinv[r], A: Mx256 fp32, W: 256x256.
// act applied if scl != nullptr: a = elu(a*scl[k] + sft[k]) (k = feature col of A).
// BM=BN=128, BK=16, 256 threads, 8 warps in 4(m) x 2(n), warp tile 32x64.
__global__ __launch_bounds__(256, 2)
void k_gemm(const float* __restrict__ A, const float* __restrict__ W,
            float* __restrict__ C, int M,
            const float* __restrict__ scl, const float* __restrict__ sft) {
    __shared__ float As_hi[128][17];
    __shared__ float As_lo[128][17];
    __shared__ float Bs_hi[16][132];
    __shared__ float Bs_lo[16][132];

    int tid = threadIdx.x;
    int brow = blockIdx.x * 128;
    int bcol = blockIdx.y * 128;

    int lane = tid & 31;
    int warp = tid >> 5;
    int wm = warp & 3;        // 0..3 -> rows wm*32
    int wn = warp >> 2;       // 0..1 -> cols wn*64
    int g  = lane >> 2;       // groupID 0..7
    int tg = lane & 3;        // thread-in-group 0..3

    // A load mapping: row = tid>>1, two float4 at cols (tid&1)*8 + {0,4}
    int aRow = tid >> 1;
    int aC   = (tid & 1) * 8;
    // B load mapping: row = tid>>4 (0..15), two float4 at cols (tid&15)*8 + {0,4}
    int bRow = tid >> 4;
    int bC   = (tid & 15) * 8;

    float acc[2][8][4];
#pragma unroll
    for (int mt = 0; mt < 2; mt++)
#pragma unroll
        for (int nt = 0; nt < 8; nt++)
#pragma unroll
            for (int j = 0; j < 4; j++) acc[mt][nt][j] = 0.f;

    for (int kt = 0; kt < 256; kt += 16) {
        // --- load A tile (with optional lazy activation) ---
        {
            int gr = brow + aRow;
#pragma unroll
            for (int h = 0; h < 2; h++) {
                int c0 = aC + h * 4;
                float4 v = make_float4(0.f, 0.f, 0.f, 0.f);
                if (gr < M) v = *(const float4*)(A + (size_t)gr * 256 + kt + c0);
                if (scl) {
                    v.x = elu_act(v.x, scl[kt + c0 + 0], sft[kt + c0 + 0]);
                    v.y = elu_act(v.y, scl[kt + c0 + 1], sft[kt + c0 + 1]);
                    v.z = elu_act(v.z, scl[kt + c0 + 2], sft[kt + c0 + 2]);
                    v.w = elu_act(v.w, scl[kt + c0 + 3], sft[kt + c0 + 3]);
                }
                float hx = __uint_as_float(f2tf32(v.x));
                float hy = __uint_as_float(f2tf32(v.y));
                float hz = __uint_as_float(f2tf32(v.z));
                float hw = __uint_as_float(f2tf32(v.w));
                As_hi[aRow][c0 + 0] = hx;
                As_hi[aRow][c0 + 1] = hy;
                As_hi[aRow][c0 + 2] = hz;
                As_hi[aRow][c0 + 3] = hw;
                As_lo[aRow][c0 + 0] = __uint_as_float(f2tf32(v.x - hx));
                As_lo[aRow][c0 + 1] = __uint_as_float(f2tf32(v.y - hy));
                As_lo[aRow][c0 + 2] = __uint_as_float(f2tf32(v.z - hz));
                As_lo[aRow][c0 + 3] = __uint_as_float(f2tf32(v.w - hw));
            }
        }
        // --- load B tile ---
        {
#pragma unroll
            for (int h = 0; h < 2; h++) {
                int c0 = bC + h * 4;
                float4 v = *(const float4*)(W + (size_t)(kt + bRow) * 256 + bcol + c0);
                float hx = __uint_as_float(f2tf32(v.x));
                float hy = __uint_as_float(f2tf32(v.y));
                float hz = __uint_as_float(f2tf32(v.z));
                float hw = __uint_as_float(f2tf32(v.w));
                Bs_hi[bRow][c0 + 0] = hx;
                Bs_hi[bRow][c0 + 1] = hy;
                Bs_hi[bRow][c0 + 2] = hz;
                Bs_hi[bRow][c0 + 3] = hw;
                Bs_lo[bRow][c0 + 0] = __uint_as_float(f2tf32(v.x - hx));
                Bs_lo[bRow][c0 + 1] = __uint_as_float(f2tf32(v.y - hy));
                Bs_lo[bRow][c0 + 2] = __uint_as_float(f2tf32(v.z - hz));
                Bs_lo[bRow][c0 + 3] = __uint_as_float(f2tf32(v.w - hw));
            }
        }
        __syncthreads();

#pragma unroll
        for (int ks = 0; ks < 2; ks++) {
            int k0 = ks * 8;
            uint32_t ah[2][4], al[2][4];
#pragma unroll
            for (int mt = 0; mt < 2; mt++) {
                int m = wm * 32 + mt * 16;
                ah[mt][0] = __float_as_uint(As_hi[m + g][k0 + tg]);
                ah[mt][1] = __float_as_uint(As_hi[m + g + 8][k0 + tg]);
                ah[mt][2] = __float_as_uint(As_hi[m + g][k0 + tg + 4]);
                ah[mt][3] = __float_as_uint(As_hi[m + g + 8][k0 + tg + 4]);
                al[mt][0] = __float_as_uint(As_lo[m + g][k0 + tg]);
                al[mt][1] = __float_as_uint(As_lo[m + g + 8][k0 + tg]);
                al[mt][2] = __float_as_uint(As_lo[m + g][k0 + tg + 4]);
                al[mt][3] = __float_as_uint(As_lo[m + g + 8][k0 + tg + 4]);
            }
#pragma unroll
            for (int nt = 0; nt < 8; nt++) {
                int nn = wn * 64 + nt * 8 + g;
                uint32_t bh[2], bl[2];
                bh[0] = __float_as_uint(Bs_hi[k0 + tg][nn]);
                bh[1] = __float_as_uint(Bs_hi[k0 + tg + 4][nn]);
                bl[0] = __float_as_uint(Bs_lo[k0 + tg][nn]);
                bl[1] = __float_as_uint(Bs_lo[k0 + tg + 4][nn]);
#pragma unroll
                for (int mt = 0; mt < 2; mt++) {
                    mma_tf32(acc[mt][nt], ah[mt], bh);
                    mma_tf32(acc[mt][nt], ah[mt], bl);
                    mma_tf32(acc[mt][nt], al[mt], bh);
                }
            }
        }
        __syncthreads();
    }

    // epilogue: scale by dinv[r], write
#pragma unroll
    for (int mt = 0; mt < 2; mt++) {
        int r0 = brow + wm * 32 + mt * 16 + g;
        int r1 = r0 + 8;
        float s0 = (r0 < M) ? g_dinv[r0] : 0.f;
        float s1 = (r1 < M) ? g_dinv[r1] : 0.f;
#pragma unroll
        for (int nt = 0; nt < 8; nt++) {
            int col = bcol + wn * 64 + nt * 8 + tg * 2;
            if (r0 < M) {
                float2 v = make_float2(acc[mt][nt][0] * s0, acc[mt][nt][1] * s0);
                *(float2*)(C + (size_t)r0 * 256 + col) = v;
            }
            if (r1 < M) {
                float2 v = make_float2(acc[mt][nt][2] * s1, acc[mt][nt][3] * s1);
                *(float2*)(C + (size_t)r1 * 256 + col) = v;
            }
        }
    }
}

// ---------------- aggregation ----------------
// z[d] = act_or_raw(prev[d]) + dinv[d]*sum_s hws[s] + bias
// 4 rows per block, 64 lanes (float4) per row.
__global__ void k_agg(const float4* __restrict__ hws, const float* __restrict__ prev,
                      const float* __restrict__ pscl, const float* __restrict__ psft,
                      const float4* __restrict__ bias, float4* __restrict__ z, int n) {
    int row = blockIdx.x * 4 + (threadIdx.x >> 6);
    if (row >= n) return;
    int lane = threadIdx.x & 63;
    int s0 = g_rowptr[row], s1 = g_rowptr[row + 1];

    float4 acc = make_float4(0.f, 0.f, 0.f, 0.f);
    float4 acc2 = make_float4(0.f, 0.f, 0.f, 0.f);
    int e = s0;
    for (; e + 1 < s1; e += 2) {
        int sa = g_csr[e];
        int sb = g_csr[e + 1];
        float4 va = hws[(size_t)sa * 64 + lane];
        float4 vb = hws[(size_t)sb * 64 + lane];
        acc.x += va.x; acc.y += va.y; acc.z += va.z; acc.w += va.w;
        acc2.x += vb.x; acc2.y += vb.y; acc2.z += vb.z; acc2.w += vb.w;
    }
    if (e < s1) {
        int sa = g_csr[e];
        float4 va = hws[(size_t)sa * 64 + lane];
        acc.x += va.x; acc.y += va.y; acc.z += va.z; acc.w += va.w;
    }
    acc.x += acc2.x; acc.y += acc2.y; acc.z += acc2.z; acc.w += acc2.w;

    float d = g_dinv[row];
    float4 b = bias[lane];
    float4 o;
    o.x = fmaf(d, acc.x, b.x);
    o.y = fmaf(d, acc.y, b.y);
    o.z = fmaf(d, acc.z, b.z);
    o.w = fmaf(d, acc.w, b.w);
    if (prev) {
        const float4* p4 = (const float4*)prev;
        float4 p = p4[(size_t)row * 64 + lane];
        if (pscl) {
            int c = lane * 4;
            o.x += elu_act(p.x, pscl[c + 0], psft[c + 0]);
            o.y += elu_act(p.y, pscl[c + 1], psft[c + 1]);
            o.z += elu_act(p.z, pscl[c + 2], psft[c + 2]);
            o.w += elu_act(p.w, pscl[c + 3], psft[c + 3]);
        } else {
            o.x += p.x; o.y += p.y; o.z += p.z; o.w += p.w;
        }
    }
    z[(size_t)row * 64 + lane] = o;
}

// ---------------- batchnorm stats ----------------
__global__ void k_stats(const float* __restrict__ z, int n) {
    int t = threadIdx.x;
    int r0 = blockIdx.x * 128;
    int r1 = min(n, r0 + 128);
    float s = 0.f, q = 0.f;
    for (int r = r0; r < r1; ++r) {
        float v = z[(size_t)r * DCOL + t];
        s += v;
        q += v * v;
    }
    atomicAdd(&g_colsum[t], s);
    atomicAdd(&g_colsq[t], q);
}

__global__ void k_bn_finalize(const float* __restrict__ gamma, const float* __restrict__ beta,
                              int n, int layer) {
    int t = threadIdx.x;
    float inv_n = 1.f / (float)n;
    float mu = g_colsum[t] * inv_n;
    float var = g_colsq[t] * inv_n - mu * mu;
    float rs = rsqrtf(var + 1e-5f);
    float sc = gamma[t] * rs;
    g_sc[layer][t] = sc;
    g_sh[layer][t] = beta[t] - mu * sc;
    g_colsum[t] = 0.f;   // ready for next layer
    g_colsq[t] = 0.f;
}

// ---------------- pool + readout (lazy act on z2) ----------------
__global__ void k_pool_out(const float* __restrict__ z, const int* __restrict__ batch,
                           const float* __restrict__ Wr, const float* __restrict__ br,
                           float* __restrict__ out, int n) {
    int gg = blockIdx.x;
    int t = threadIdx.x;
    int lo = 0, hi = n;
    while (lo < hi) { int m = (lo + hi) >> 1; if (batch[m] < gg) lo = m + 1; else hi = m; }
    int start = lo;
    lo = start; hi = n;
    while (lo < hi) { int m = (lo + hi) >> 1; if (batch[m] < gg + 1) lo = m + 1; else hi = m; }
    int end = lo;

    float sc = g_sc[2][t], sh = g_sh[2][t];
    float sum = 0.f;
    for (int r = start; r < end; ++r)
        sum += elu_act(z[(size_t)r * DCOL + t], sc, sh);
    float cnt = (float)(end - start);
    float v = sum / fmaxf(cnt, 1.f);

    __shared__ float red[DCOL];
    for (int c = 0; c < 2; ++c) {
        red[t] = v * Wr[t * 2 + c];
        __syncthreads();
        for (int s = 128; s > 0; s >>= 1) {
            if (t < s) red[t] += red[t + s];
            __syncthreads();
        }
        if (t == 0) out[gg * 2 + c] = red[0] + br[c];
        __syncthreads();
    }
}

// ---------------- launch ----------------
extern "C" void kernel_launch(void* const* d_in, const int* in_sizes, int n_in,
                              void* d_out, int out_size) {
    const float* x     = (const float*)d_in[0];
    const int*   ei    = (const int*)d_in[1];
    const int*   batch = (const int*)d_in[2];
    const float* W[3]     = { (const float*)d_in[3],  (const float*)d_in[7],  (const float*)d_in[11] };
    const float* b[3]     = { (const float*)d_in[4],  (const float*)d_in[8],  (const float*)d_in[12] };
    const float* gamma[3] = { (const float*)d_in[5],  (const float*)d_in[9],  (const float*)d_in[13] };
    const float* beta[3]  = { (const float*)d_in[6],  (const float*)d_in[10], (const float*)d_in[14] };
    const float* Wr = (const float*)d_in[15];
    const float* br = (const float*)d_in[16];
    float* out = (float*)d_out;

    int n = in_sizes[0] / DCOL;
    int e = in_sizes[1] / 2;
    int g = out_size / 2;
    const int* src = ei;
    const int* dst = ei + e;

    float *p_hw, *p_z0, *p_z1, *p_sc, *p_sh;
    cudaGetSymbolAddress((void**)&p_hw, g_hw);
    cudaGetSymbolAddress((void**)&p_z0, g_h1);
    cudaGetSymbolAddress((void**)&p_z1, g_h2);
    cudaGetSymbolAddress((void**)&p_sc, g_sc);
    cudaGetSymbolAddress((void**)&p_sh, g_sh);

    // ---- preprocessing ----
    int nb256_n = (n + 255) / 256;
    int nb256_e = (e + 255) / 256;
    int nb1024  = (n + 1023) / 1024;

    k_init_deg<<<nb256_n, 256>>>(n);
    k_count_deg<<<nb256_e, 256>>>(dst, e);
    k_dinv<<<nb256_n, 256>>>(n);
    k_scan_block<<<nb1024, 1024>>>(n);
    k_scan_sums<<<1, 32>>>(nb1024);
    k_scan_final<<<nb1024, 1024>>>(n);
    k_fill_csr<<<nb256_e, 256>>>(src, dst, e);
    k_fill_self<<<nb256_n, 256>>>(n);

    dim3 gemm_grid((n + 127) / 128, 2);
    int nb_agg   = (n + 3) / 4;
    int nb_stats = (n + 127) / 128;

    // ---- layer 0: A=x raw, prev=none -> z0 ----
    k_gemm<<<gemm_grid, 256>>>(x, W[0], p_hw, n, nullptr, nullptr);
    k_agg<<<nb_agg, 256>>>((const float4*)p_hw, nullptr, nullptr, nullptr,
                           (const float4*)b[0], (float4*)p_z0, n);
    k_stats<<<nb_stats, 256>>>(p_z0, n);
    k_bn_finalize<<<1, 256>>>(gamma[0], beta[0], n, 0);

    // ---- layer 1: A=act0(z0), prev=x raw -> z1 ----
    k_gemm<<<gemm_grid, 256>>>(p_z0, W[1], p_hw, n, p_sc + 0 * DCOL, p_sh + 0 * DCOL);
    k_agg<<<nb_agg, 256>>>((const float4*)p_hw, x, nullptr, nullptr,
                           (const float4*)b[1], (float4*)p_z1, n);
    k_stats<<<nb_stats, 256>>>(p_z1, n);
    k_bn_finalize<<<1, 256>>>(gamma[1], beta[1], n, 1);

    // ---- layer 2: A=act1(z1), prev=act0(z0) -> z2 (overwrites z0, elementwise safe) ----
    k_gemm<<<gemm_grid, 256>>>(p_z1, W[2], p_hw, n, p_sc + 1 * DCOL, p_sh + 1 * DCOL);
    k_agg<<<nb_agg, 256>>>((const float4*)p_hw, p_z0, p_sc + 0 * DCOL, p_sh + 0 * DCOL,
                           (const float4*)b[2], (float4*)p_z0, n);
    k_stats<<<nb_stats, 256>>>(p_z0, n);
    k_bn_finalize<<<1, 256>>>(gamma[2], beta[2], n, 2);

    // ---- pool + readout (act2 lazy) ----
    k_pool_out<<<g, 256>>>(p_z0, batch, Wr, br, out, n);
}

// round 4
// speedup vs baseline: 1.3179x; 1.0197x over previous
#include <cuda_runtime.h>
#include <cuda_fp16.h>
#include <cstdint>
#include <math.h>

#define MAXN 65536
#define MAXE (1 << 21)
#define DCOL 256

// ---------------- static device scratch ----------------
__device__ __half2 g_hw[MAXN * (DCOL / 2)];  // (h @ W) * dinv[row], fp16
__device__ float g_h1[MAXN * DCOL];   // z0 / z2
__device__ float g_h2[MAXN * DCOL];   // z1
__device__ int   g_deg[MAXN];
__device__ int   g_scan[MAXN];
__device__ int   g_rowptr[MAXN + 1];
__device__ int   g_cursor[MAXN];
__device__ int   g_csr[MAXE];
__device__ int   g_bsums[128];
__device__ float g_dinv[MAXN];
__device__ float g_colsum[DCOL];
__device__ float g_colsq[DCOL];
__device__ float g_sc[3][DCOL];   // per-layer BN scale
__device__ float g_sh[3][DCOL];   // per-layer BN shift

__device__ __forceinline__ float elu_act(float z, float sc, float sh) {
    float v = fmaf(z, sc, sh);
    return v > 0.f ? v : expm1f(v);
}

__device__ __forceinline__ uint32_t f2tf32(float x) {
    uint32_t r;
    asm("cvt.rna.tf32.f32 %0, %1;" : "=r"(r) : "f"(x));
    return r;
}

__device__ __forceinline__ void mma_tf32(float* d, const uint32_t* a, const uint32_t* b) {
    asm volatile(
        "mma.sync.aligned.m16n8k8.row.col.f32.tf32.tf32.f32 "
        "{%0,%1,%2,%3},{%4,%5,%6,%7},{%8,%9},{%0,%1,%2,%3};"
        : "+f"(d[0]), "+f"(d[1]), "+f"(d[2]), "+f"(d[3])
        : "r"(a[0]), "r"(a[1]), "r"(a[2]), "r"(a[3]), "r"(b[0]), "r"(b[1]));
}

// unpack 4 halves (as float2 bits) into float4
__device__ __forceinline__ float4 h4_to_f4(float2 p) {
    __half2 h0 = *reinterpret_cast<__half2*>(&p.x);
    __half2 h1 = *reinterpret_cast<__half2*>(&p.y);
    float2 a = __half22float2(h0);
    float2 b = __half22float2(h1);
    return make_float4(a.x, a.y, b.x, b.y);
}

// ---------------- preprocessing ----------------
__global__ void k_init_deg(int n) {
    int i = blockIdx.x * blockDim.x + threadIdx.x;
    if (i < n) g_deg[i] = 1;  // self loop
    if (blockIdx.x == 0 && threadIdx.x < DCOL) {
        g_colsum[threadIdx.x] = 0.f;
        g_colsq[threadIdx.x] = 0.f;
    }
}

__global__ void k_count_deg(const int* __restrict__ dst, int e) {
    int i = blockIdx.x * blockDim.x + threadIdx.x;
    if (i < e) atomicAdd(&g_deg[dst[i]], 1);
}

__global__ void k_dinv(int n) {
    int i = blockIdx.x * blockDim.x + threadIdx.x;
    if (i < n) g_dinv[i] = rsqrtf((float)g_deg[i]);
}

__global__ void k_scan_block(int n) {
    __shared__ int sh[1024];
    int i = blockIdx.x * 1024 + threadIdx.x;
    int v = (i < n) ? g_deg[i] : 0;
    sh[threadIdx.x] = v;
    __syncthreads();
    for (int off = 1; off < 1024; off <<= 1) {
        int t = (threadIdx.x >= off) ? sh[threadIdx.x - off] : 0;
        __syncthreads();
        sh[threadIdx.x] += t;
        __syncthreads();
    }
    if (i < n) g_scan[i] = sh[threadIdx.x];
    if (threadIdx.x == 1023) g_bsums[blockIdx.x] = sh[1023];
}

__global__ void k_scan_sums(int nb) {
    if (threadIdx.x == 0 && blockIdx.x == 0) {
        int acc = 0;
        for (int i = 0; i < nb; i++) { acc += g_bsums[i]; g_bsums[i] = acc; }
    }
}

__global__ void k_scan_final(int n) {
    int i = blockIdx.x * 1024 + threadIdx.x;
    if (i < n) {
        int off = (blockIdx.x > 0) ? g_bsums[blockIdx.x - 1] : 0;
        int incl = g_scan[i] + off;
        g_rowptr[i + 1] = incl;
        g_cursor[i] = incl - g_deg[i];
        if (i == 0) g_rowptr[0] = 0;
    }
}

__global__ void k_fill_csr(const int* __restrict__ src, const int* __restrict__ dst, int e) {
    int i = blockIdx.x * blockDim.x + threadIdx.x;
    if (i < e) {
        int d = dst[i];
        int p = atomicAdd(&g_cursor[d], 1);
        g_csr[p] = src[i];
    }
}

__global__ void k_fill_self(int n) {
    int i = blockIdx.x * blockDim.x + threadIdx.x;
    if (i < n) {
        int p = atomicAdd(&g_cursor[i], 1);
        g_csr[p] = i;
    }
}

// ---------------- TF32x3 tensor-core GEMM ----------------
// Chw[r][c] = fp16( (act(A) @ W)[r][c] * dinv[r] ), A: Mx256 fp32, W: 256x256.
// act applied if scl != nullptr: a = elu(a*scl[k] + sft[k]).
// BM=BN=128, BK=16, 256 threads, 8 warps in 4(m) x 2(n), warp tile 32x64.
__global__ __launch_bounds__(256, 2)
void k_gemm(const float* __restrict__ A, const float* __restrict__ W,
            __half2* __restrict__ C, int M,
            const float* __restrict__ scl, const float* __restrict__ sft) {
    __shared__ float As_hi[128][17];
    __shared__ float As_lo[128][17];
    __shared__ float Bs_hi[16][132];
    __shared__ float Bs_lo[16][132];

    int tid = threadIdx.x;
    int brow = blockIdx.x * 128;
    int bcol = blockIdx.y * 128;

    int lane = tid & 31;
    int warp = tid >> 5;
    int wm = warp & 3;
    int wn = warp >> 2;
    int g  = lane >> 2;
    int tg = lane & 3;

    int aRow = tid >> 1;
    int aC   = (tid & 1) * 8;
    int bRow = tid >> 4;
    int bC   = (tid & 15) * 8;

    float acc[2][8][4];
#pragma unroll
    for (int mt = 0; mt < 2; mt++)
#pragma unroll
        for (int nt = 0; nt < 8; nt++)
#pragma unroll
            for (int j = 0; j < 4; j++) acc[mt][nt][j] = 0.f;

    for (int kt = 0; kt < 256; kt += 16) {
        {
            int gr = brow + aRow;
#pragma unroll
            for (int h = 0; h < 2; h++) {
                int c0 = aC + h * 4;
                float4 v = make_float4(0.f, 0.f, 0.f, 0.f);
                if (gr < M) v = *(const float4*)(A + (size_t)gr * 256 + kt + c0);
                if (scl) {
                    v.x = elu_act(v.x, scl[kt + c0 + 0], sft[kt + c0 + 0]);
                    v.y = elu_act(v.y, scl[kt + c0 + 1], sft[kt + c0 + 1]);
                    v.z = elu_act(v.z, scl[kt + c0 + 2], sft[kt + c0 + 2]);
                    v.w = elu_act(v.w, scl[kt + c0 + 3], sft[kt + c0 + 3]);
                }
                float hx = __uint_as_float(f2tf32(v.x));
                float hy = __uint_as_float(f2tf32(v.y));
                float hz = __uint_as_float(f2tf32(v.z));
                float hw = __uint_as_float(f2tf32(v.w));
                As_hi[aRow][c0 + 0] = hx;
                As_hi[aRow][c0 + 1] = hy;
                As_hi[aRow][c0 + 2] = hz;
                As_hi[aRow][c0 + 3] = hw;
                As_lo[aRow][c0 + 0] = __uint_as_float(f2tf32(v.x - hx));
                As_lo[aRow][c0 + 1] = __uint_as_float(f2tf32(v.y - hy));
                As_lo[aRow][c0 + 2] = __uint_as_float(f2tf32(v.z - hz));
                As_lo[aRow][c0 + 3] = __uint_as_float(f2tf32(v.w - hw));
            }
        }
        {
#pragma unroll
            for (int h = 0; h < 2; h++) {
                int c0 = bC + h * 4;
                float4 v = *(const float4*)(W + (size_t)(kt + bRow) * 256 + bcol + c0);
                float hx = __uint_as_float(f2tf32(v.x));
                float hy = __uint_as_float(f2tf32(v.y));
                float hz = __uint_as_float(f2tf32(v.z));
                float hw = __uint_as_float(f2tf32(v.w));
                Bs_hi[bRow][c0 + 0] = hx;
                Bs_hi[bRow][c0 + 1] = hy;
                Bs_hi[bRow][c0 + 2] = hz;
                Bs_hi[bRow][c0 + 3] = hw;
                Bs_lo[bRow][c0 + 0] = __uint_as_float(f2tf32(v.x - hx));
                Bs_lo[bRow][c0 + 1] = __uint_as_float(f2tf32(v.y - hy));
                Bs_lo[bRow][c0 + 2] = __uint_as_float(f2tf32(v.z - hz));
                Bs_lo[bRow][c0 + 3] = __uint_as_float(f2tf32(v.w - hw));
            }
        }
        __syncthreads();

#pragma unroll
        for (int ks = 0; ks < 2; ks++) {
            int k0 = ks * 8;
            uint32_t ah[2][4], al[2][4];
#pragma unroll
            for (int mt = 0; mt < 2; mt++) {
                int m = wm * 32 + mt * 16;
                ah[mt][0] = __float_as_uint(As_hi[m + g][k0 + tg]);
                ah[mt][1] = __float_as_uint(As_hi[m + g + 8][k0 + tg]);
                ah[mt][2] = __float_as_uint(As_hi[m + g][k0 + tg + 4]);
                ah[mt][3] = __float_as_uint(As_hi[m + g + 8][k0 + tg + 4]);
                al[mt][0] = __float_as_uint(As_lo[m + g][k0 + tg]);
                al[mt][1] = __float_as_uint(As_lo[m + g + 8][k0 + tg]);
                al[mt][2] = __float_as_uint(As_lo[m + g][k0 + tg + 4]);
                al[mt][3] = __float_as_uint(As_lo[m + g + 8][k0 + tg + 4]);
            }
#pragma unroll
            for (int nt = 0; nt < 8; nt++) {
                int nn = wn * 64 + nt * 8 + g;
                uint32_t bh[2], bl[2];
                bh[0] = __float_as_uint(Bs_hi[k0 + tg][nn]);
                bh[1] = __float_as_uint(Bs_hi[k0 + tg + 4][nn]);
                bl[0] = __float_as_uint(Bs_lo[k0 + tg][nn]);
                bl[1] = __float_as_uint(Bs_lo[k0 + tg + 4][nn]);
#pragma unroll
                for (int mt = 0; mt < 2; mt++) {
                    mma_tf32(acc[mt][nt], ah[mt], bh);
                    mma_tf32(acc[mt][nt], ah[mt], bl);
                    mma_tf32(acc[mt][nt], al[mt], bh);
                }
            }
        }
        __syncthreads();
    }

    // epilogue: scale by dinv[r], convert to fp16, write half2
#pragma unroll
    for (int mt = 0; mt < 2; mt++) {
        int r0 = brow + wm * 32 + mt * 16 + g;
        int r1 = r0 + 8;
        float s0 = (r0 < M) ? g_dinv[r0] : 0.f;
        float s1 = (r1 < M) ? g_dinv[r1] : 0.f;
#pragma unroll
        for (int nt = 0; nt < 8; nt++) {
            int col = bcol + wn * 64 + nt * 8 + tg * 2;  // even
            if (r0 < M)
                C[(size_t)r0 * 128 + (col >> 1)] =
                    __floats2half2_rn(acc[mt][nt][0] * s0, acc[mt][nt][1] * s0);
            if (r1 < M)
                C[(size_t)r1 * 128 + (col >> 1)] =
                    __floats2half2_rn(acc[mt][nt][2] * s1, acc[mt][nt][3] * s1);
        }
    }
}

// ---------------- aggregation ----------------
// z[d] = act_or_raw(prev[d]) + dinv[d]*sum_s hw16[s] + bias
// 4 rows per block, 64 lanes per row; each lane owns 4 halves (one float2 load).
__global__ void k_agg(const float2* __restrict__ hws, const float* __restrict__ prev,
                      const float* __restrict__ pscl, const float* __restrict__ psft,
                      const float4* __restrict__ bias, float4* __restrict__ z, int n) {
    int row = blockIdx.x * 4 + (threadIdx.x >> 6);
    if (row >= n) return;
    int lane = threadIdx.x & 63;
    int s0 = g_rowptr[row], s1 = g_rowptr[row + 1];

    float4 a0 = make_float4(0.f, 0.f, 0.f, 0.f);
    float4 a1 = make_float4(0.f, 0.f, 0.f, 0.f);
    float4 a2 = make_float4(0.f, 0.f, 0.f, 0.f);
    float4 a3 = make_float4(0.f, 0.f, 0.f, 0.f);

    int e = s0;
    for (; e + 3 < s1; e += 4) {
        int sa = g_csr[e + 0];
        int sb = g_csr[e + 1];
        int sc = g_csr[e + 2];
        int sd = g_csr[e + 3];
        float2 pa = hws[(size_t)sa * 64 + lane];
        float2 pb = hws[(size_t)sb * 64 + lane];
        float2 pc = hws[(size_t)sc * 64 + lane];
        float2 pd = hws[(size_t)sd * 64 + lane];
        float4 va = h4_to_f4(pa);
        float4 vb = h4_to_f4(pb);
        float4 vc = h4_to_f4(pc);
        float4 vd = h4_to_f4(pd);
        a0.x += va.x; a0.y += va.y; a0.z += va.z; a0.w += va.w;
        a1.x += vb.x; a1.y += vb.y; a1.z += vb.z; a1.w += vb.w;
        a2.x += vc.x; a2.y += vc.y; a2.z += vc.z; a2.w += vc.w;
        a3.x += vd.x; a3.y += vd.y; a3.z += vd.z; a3.w += vd.w;
    }
    for (; e < s1; ++e) {
        int sa = g_csr[e];
        float4 va = h4_to_f4(hws[(size_t)sa * 64 + lane]);
        a0.x += va.x; a0.y += va.y; a0.z += va.z; a0.w += va.w;
    }
    a0.x += a1.x + a2.x + a3.x;
    a0.y += a1.y + a2.y + a3.y;
    a0.z += a1.z + a2.z + a3.z;
    a0.w += a1.w + a2.w + a3.w;

    float d = g_dinv[row];
    float4 b = bias[lane];
    float4 o;
    o.x = fmaf(d, a0.x, b.x);
    o.y = fmaf(d, a0.y, b.y);
    o.z = fmaf(d, a0.z, b.z);
    o.w = fmaf(d, a0.w, b.w);
    if (prev) {
        const float4* p4 = (const float4*)prev;
        float4 p = p4[(size_t)row * 64 + lane];
        if (pscl) {
            int c = lane * 4;
            o.x += elu_act(p.x, pscl[c + 0], psft[c + 0]);
            o.y += elu_act(p.y, pscl[c + 1], psft[c + 1]);
            o.z += elu_act(p.z, pscl[c + 2], psft[c + 2]);
            o.w += elu_act(p.w, pscl[c + 3], psft[c + 3]);
        } else {
            o.x += p.x; o.y += p.y; o.z += p.z; o.w += p.w;
        }
    }
    z[(size_t)row * 64 + lane] = o;
}

// ---------------- batchnorm stats ----------------
__global__ void k_stats(const float* __restrict__ z, int n) {
    int t = threadIdx.x;
    int r0 = blockIdx.x * 128;
    int r1 = min(n, r0 + 128);
    float s = 0.f, q = 0.f;
    for (int r = r0; r < r1; ++r) {
        float v = z[(size_t)r * DCOL + t];
        s += v;
        q += v * v;
    }
    atomicAdd(&g_colsum[t], s);
    atomicAdd(&g_colsq[t], q);
}

__global__ void k_bn_finalize(const float* __restrict__ gamma, const float* __restrict__ beta,
                              int n, int layer) {
    int t = threadIdx.x;
    float inv_n = 1.f / (float)n;
    float mu = g_colsum[t] * inv_n;
    float var = g_colsq[t] * inv_n - mu * mu;
    float rs = rsqrtf(var + 1e-5f);
    float sc = gamma[t] * rs;
    g_sc[layer][t] = sc;
    g_sh[layer][t] = beta[t] - mu * sc;
    g_colsum[t] = 0.f;   // ready for next layer
    g_colsq[t] = 0.f;
}

// ---------------- pool + readout (lazy act on z2) ----------------
__global__ void k_pool_out(const float* __restrict__ z, const int* __restrict__ batch,
                           const float* __restrict__ Wr, const float* __restrict__ br,
                           float* __restrict__ out, int n) {
    int gg = blockIdx.x;
    int t = threadIdx.x;
    int lo = 0, hi = n;
    while (lo < hi) { int m = (lo + hi) >> 1; if (batch[m] < gg) lo = m + 1; else hi = m; }
    int start = lo;
    lo = start; hi = n;
    while (lo < hi) { int m = (lo + hi) >> 1; if (batch[m] < gg + 1) lo = m + 1; else hi = m; }
    int end = lo;

    float sc = g_sc[2][t], sh = g_sh[2][t];
    float sum = 0.f;
    for (int r = start; r < end; ++r)
        sum += elu_act(z[(size_t)r * DCOL + t], sc, sh);
    float cnt = (float)(end - start);
    float v = sum / fmaxf(cnt, 1.f);

    __shared__ float red[DCOL];
    for (int c = 0; c < 2; ++c) {
        red[t] = v * Wr[t * 2 + c];
        __syncthreads();
        for (int s = 128; s > 0; s >>= 1) {
            if (t < s) red[t] += red[t + s];
            __syncthreads();
        }
        if (t == 0) out[gg * 2 + c] = red[0] + br[c];
        __syncthreads();
    }
}

// ---------------- launch ----------------
extern "C" void kernel_launch(void* const* d_in, const int* in_sizes, int n_in,
                              void* d_out, int out_size) {
    const float* x     = (const float*)d_in[0];
    const int*   ei    = (const int*)d_in[1];
    const int*   batch = (const int*)d_in[2];
    const float* W[3]     = { (const float*)d_in[3],  (const float*)d_in[7],  (const float*)d_in[11] };
    const float* b[3]     = { (const float*)d_in[4],  (const float*)d_in[8],  (const float*)d_in[12] };
    const float* gamma[3] = { (const float*)d_in[5],  (const float*)d_in[9],  (const float*)d_in[13] };
    const float* beta[3]  = { (const float*)d_in[6],  (const float*)d_in[10], (const float*)d_in[14] };
    const float* Wr = (const float*)d_in[15];
    const float* br = (const float*)d_in[16];
    float* out = (float*)d_out;

    int n = in_sizes[0] / DCOL;
    int e = in_sizes[1] / 2;
    int g = out_size / 2;
    const int* src = ei;
    const int* dst = ei + e;

    __half2* p_hw;
    float *p_z0, *p_z1, *p_sc, *p_sh;
    cudaGetSymbolAddress((void**)&p_hw, g_hw);
    cudaGetSymbolAddress((void**)&p_z0, g_h1);
    cudaGetSymbolAddress((void**)&p_z1, g_h2);
    cudaGetSymbolAddress((void**)&p_sc, g_sc);
    cudaGetSymbolAddress((void**)&p_sh, g_sh);

    // ---- preprocessing ----
    int nb256_n = (n + 255) / 256;
    int nb256_e = (e + 255) / 256;
    int nb1024  = (n + 1023) / 1024;

    k_init_deg<<<nb256_n, 256>>>(n);
    k_count_deg<<<nb256_e, 256>>>(dst, e);
    k_dinv<<<nb256_n, 256>>>(n);
    k_scan_block<<<nb1024, 1024>>>(n);
    k_scan_sums<<<1, 32>>>(nb1024);
    k_scan_final<<<nb1024, 1024>>>(n);
    k_fill_csr<<<nb256_e, 256>>>(src, dst, e);
    k_fill_self<<<nb256_n, 256>>>(n);

    dim3 gemm_grid((n + 127) / 128, 2);
    int nb_agg   = (n + 3) / 4;
    int nb_stats = (n + 127) / 128;

    // ---- layer 0: A=x raw, prev=none -> z0 ----
    k_gemm<<<gemm_grid, 256>>>(x, W[0], p_hw, n, nullptr, nullptr);
    k_agg<<<nb_agg, 256>>>((const float2*)p_hw, nullptr, nullptr, nullptr,
                           (const float4*)b[0], (float4*)p_z0, n);
    k_stats<<<nb_stats, 256>>>(p_z0, n);
    k_bn_finalize<<<1, 256>>>(gamma[0], beta[0], n, 0);

    // ---- layer 1: A=act0(z0), prev=x raw -> z1 ----
    k_gemm<<<gemm_grid, 256>>>(p_z0, W[1], p_hw, n, p_sc + 0 * DCOL, p_sh + 0 * DCOL);
    k_agg<<<nb_agg, 256>>>((const float2*)p_hw, x, nullptr, nullptr,
                           (const float4*)b[1], (float4*)p_z1, n);
    k_stats<<<nb_stats, 256>>>(p_z1, n);
    k_bn_finalize<<<1, 256>>>(gamma[1], beta[1], n, 1);

    // ---- layer 2: A=act1(z1), prev=act0(z0) -> z2 (overwrites z0, elementwise safe) ----
    k_gemm<<<gemm_grid, 256>>>(p_z1, W[2], p_hw, n, p_sc + 1 * DCOL, p_sh + 1 * DCOL);
    k_agg<<<nb_agg, 256>>>((const float2*)p_hw, p_z0, p_sc + 0 * DCOL, p_sh + 0 * DCOL,
                           (const float4*)b[2], (float4*)p_z0, n);
    k_stats<<<nb_stats, 256>>>(p_z0, n);
    k_bn_finalize<<<1, 256>>>(gamma[2], beta[2], n, 2);

    // ---- pool + readout (act2 lazy) ----
    k_pool_out<<<g, 256>>>(p_z0, batch, Wr, br, out, n);
}

// round 6
// speedup vs baseline: 1.7320x; 1.3142x over previous
#include <cuda_runtime.h>
#include <cuda_fp16.h>
#include <cstdint>
#include <math.h>

#define MAXN 65536
#define MAXE (1 << 21)
#define DCOL 256

// ---------------- static device scratch ----------------
__device__ __half2 g_hw[MAXN * (DCOL / 2)];  // (h @ W) * dinv[row], fp16
__device__ float g_h1[MAXN * DCOL];   // z0 / z2
__device__ float g_h2[MAXN * DCOL];   // z1
__device__ int   g_deg[MAXN];         // starts 0 (static init); re-zeroed by k_agg each call
__device__ int   g_scan[MAXN];
__device__ int   g_rowptr[MAXN + 1];
__device__ int   g_cursor[MAXN];
__device__ int   g_csr[MAXE];
__device__ int   g_bsums[128];
__device__ float g_dinv[MAXN];
__device__ float g_colsum[DCOL];      // starts 0; re-zeroed by bn_finalize
__device__ float g_colsq[DCOL];
__device__ float g_sc[3][DCOL];
__device__ float g_sh[3][DCOL];
__device__ __half g_Whi[3][DCOL * DCOL];  // W split hi, transposed [n][k]
__device__ __half g_Wlo[3][DCOL * DCOL];  // W split lo, transposed [n][k]

__device__ __forceinline__ float elu_act(float z, float sc, float sh) {
    float v = fmaf(z, sc, sh);
    return v > 0.f ? v : expm1f(v);
}

__device__ __forceinline__ void mma16816(float* d, const uint32_t* a, const uint32_t* b) {
    asm volatile(
        "mma.sync.aligned.m16n8k16.row.col.f32.f16.f16.f32 "
        "{%0,%1,%2,%3},{%4,%5,%6,%7},{%8,%9},{%0,%1,%2,%3};"
        : "+f"(d[0]), "+f"(d[1]), "+f"(d[2]), "+f"(d[3])
        : "r"(a[0]), "r"(a[1]), "r"(a[2]), "r"(a[3]), "r"(b[0]), "r"(b[1]));
}

// unpack 4 halves (as float2 bits) into float4
__device__ __forceinline__ float4 h4_to_f4(float2 p) {
    __half2 h0 = *reinterpret_cast<__half2*>(&p.x);
    __half2 h1 = *reinterpret_cast<__half2*>(&p.y);
    float2 a = __half22float2(h0);
    float2 b = __half22float2(h1);
    return make_float4(a.x, a.y, b.x, b.y);
}

// ---------------- preprocessing (exactly 5 launches before first GEMM) ----------------
// launch 1: count degrees (g_deg starts zeroed)
__global__ void k_count_deg(const int* __restrict__ dst, int e) {
    int i = blockIdx.x * blockDim.x + threadIdx.x;
    if (i < e) atomicAdd(&g_deg[dst[i]], 1);
}

// launch 2: add self loop, dinv, block-level inclusive scan
__global__ void k_scan_block(int n) {
    __shared__ int sh[1024];
    int i = blockIdx.x * 1024 + threadIdx.x;
    int v = 0;
    if (i < n) {
        v = g_deg[i] + 1;          // + self loop
        g_deg[i] = v;
        g_dinv[i] = rsqrtf((float)v);
    }
    sh[threadIdx.x] = v;
    __syncthreads();
    for (int off = 1; off < 1024; off <<= 1) {
        int t = (threadIdx.x >= off) ? sh[threadIdx.x - off] : 0;
        __syncthreads();
        sh[threadIdx.x] += t;
        __syncthreads();
    }
    if (i < n) g_scan[i] = sh[threadIdx.x];
    if (threadIdx.x == 1023) g_bsums[blockIdx.x] = sh[1023];
}

// launch 3: serial scan of block sums (block 0) + W hi/lo split-transpose (other blocks)
__global__ void k_scan_sums_prepW(int nb, const float* __restrict__ W0,
                                  const float* __restrict__ W1, const float* __restrict__ W2) {
    if (blockIdx.x == 0) {
        if (threadIdx.x == 0) {
            int acc = 0;
            for (int i = 0; i < nb; i++) { acc += g_bsums[i]; g_bsums[i] = acc; }
        }
        return;
    }
    int idx = (blockIdx.x - 1) * 256 + threadIdx.x;   // 0 .. 3*65536-1
    int layer = idx >> 16;
    int rem = idx & 65535;           // rem = k*256 + n
    int k = rem >> 8;
    int nn = rem & 255;
    const float* Ws = (layer == 0) ? W0 : (layer == 1) ? W1 : W2;
    float w = Ws[rem];
    __half hi = __float2half_rn(w);
    __half lo = __float2half_rn(w - __half2float(hi));
    g_Whi[layer][nn * 256 + k] = hi;
    g_Wlo[layer][nn * 256 + k] = lo;
}

// launch 4: finalize rowptr + cursors
__global__ void k_scan_final(int n) {
    int i = blockIdx.x * 1024 + threadIdx.x;
    if (i < n) {
        int off = (blockIdx.x > 0) ? g_bsums[blockIdx.x - 1] : 0;
        int incl = g_scan[i] + off;
        g_rowptr[i + 1] = incl;
        g_cursor[i] = incl - g_deg[i];
        if (i == 0) g_rowptr[0] = 0;
    }
}

// launch 5: fill CSR with edges + self loops
__global__ void k_fill(const int* __restrict__ src, const int* __restrict__ dst, int e, int n) {
    int i = blockIdx.x * blockDim.x + threadIdx.x;
    if (i < e) {
        int d = dst[i];
        int p = atomicAdd(&g_cursor[d], 1);
        g_csr[p] = src[i];
    } else if (i - e < n) {
        int j = i - e;
        int p = atomicAdd(&g_cursor[j], 1);
        g_csr[p] = j;
    }
}

// ---------------- fp16x2-split tensor-core GEMM ----------------
// Chw[r][c] = fp16( (act(A) @ W)[r][c] * dinv[r] ), A: Mx256 fp32.
// Whi/Wlo pre-split, transposed [n][k]. 3-term mma: hi*hi + hi*lo + lo*hi.
// BM=BN=128, BK=32, 256 threads, 8 warps 4(m)x2(n), warp tile 32x64.
__global__ __launch_bounds__(256, 2)
void k_gemm(const float* __restrict__ A,
            const __half* __restrict__ Whi, const __half* __restrict__ Wlo,
            __half2* __restrict__ C, int M,
            const float* __restrict__ scl, const float* __restrict__ sft) {
    __shared__ __half Ah[128][40];
    __shared__ __half Al[128][40];
    __shared__ __half Bh[128][40];   // [n][k]
    __shared__ __half Bl[128][40];

    int tid = threadIdx.x;
    int brow = blockIdx.x * 128;
    int bcol = blockIdx.y * 128;

    int lane = tid & 31;
    int warp = tid >> 5;
    int wm = warp & 3;
    int wn = warp >> 2;
    int g  = lane >> 2;
    int tg = lane & 3;

    int ldRow = tid >> 1;         // 0..127 (for both A and B loads)
    int aCbase = (tid & 1) * 16;  // A: 4 float4 at cols aCbase + {0,4,8,12}
    int bCbase = (tid & 1) * 16;  // B: 2 float4(=8 halves) at cols bCbase + {0,8}

    float acc[2][8][4];
#pragma unroll
    for (int mt = 0; mt < 2; mt++)
#pragma unroll
        for (int nt = 0; nt < 8; nt++)
#pragma unroll
            for (int j = 0; j < 4; j++) acc[mt][nt][j] = 0.f;

    for (int kt = 0; kt < 256; kt += 32) {
        // ---- A: load fp32, (optional act), split into hi/lo halves ----
        {
            int gr = brow + ldRow;
#pragma unroll
            for (int i = 0; i < 4; i++) {
                int c0 = aCbase + i * 4;
                float4 v = make_float4(0.f, 0.f, 0.f, 0.f);
                if (gr < M) v = *(const float4*)(A + (size_t)gr * 256 + kt + c0);
                if (scl) {
                    v.x = elu_act(v.x, scl[kt + c0 + 0], sft[kt + c0 + 0]);
                    v.y = elu_act(v.y, scl[kt + c0 + 1], sft[kt + c0 + 1]);
                    v.z = elu_act(v.z, scl[kt + c0 + 2], sft[kt + c0 + 2]);
                    v.w = elu_act(v.w, scl[kt + c0 + 3], sft[kt + c0 + 3]);
                }
                __half hx = __float2half_rn(v.x);
                __half hy = __float2half_rn(v.y);
                __half hz = __float2half_rn(v.z);
                __half hw = __float2half_rn(v.w);
                *(__half2*)&Ah[ldRow][c0]     = __halves2half2(hx, hy);
                *(__half2*)&Ah[ldRow][c0 + 2] = __halves2half2(hz, hw);
                __half lx = __float2half_rn(v.x - __half2float(hx));
                __half ly = __float2half_rn(v.y - __half2float(hy));
                __half lz = __float2half_rn(v.z - __half2float(hz));
                __half lw = __float2half_rn(v.w - __half2float(hw));
                *(__half2*)&Al[ldRow][c0]     = __halves2half2(lx, ly);
                *(__half2*)&Al[ldRow][c0 + 2] = __halves2half2(lz, lw);
            }
        }
        // ---- B: straight half copies from pre-split W ----
        {
            const __half* sh_ = Whi + (size_t)(bcol + ldRow) * 256 + kt;
            const __half* sl_ = Wlo + (size_t)(bcol + ldRow) * 256 + kt;
#pragma unroll
            for (int i = 0; i < 2; i++) {
                int hc = bCbase + i * 8;
                *(float4*)&Bh[ldRow][hc] = *(const float4*)(sh_ + hc);
                *(float4*)&Bl[ldRow][hc] = *(const float4*)(sl_ + hc);
            }
        }
        __syncthreads();

#pragma unroll
        for (int ks = 0; ks < 2; ks++) {
            int k0 = ks * 16;
            uint32_t ah[2][4], al[2][4];
#pragma unroll
            for (int mt = 0; mt < 2; mt++) {
                int m = wm * 32 + mt * 16;
                ah[mt][0] = *(const uint32_t*)&Ah[m + g][k0 + 2 * tg];
                ah[mt][1] = *(const uint32_t*)&Ah[m + g + 8][k0 + 2 * tg];
                ah[mt][2] = *(const uint32_t*)&Ah[m + g][k0 + 2 * tg + 8];
                ah[mt][3] = *(const uint32_t*)&Ah[m + g + 8][k0 + 2 * tg + 8];
                al[mt][0] = *(const uint32_t*)&Al[m + g][k0 + 2 * tg];
                al[mt][1] = *(const uint32_t*)&Al[m + g + 8][k0 + 2 * tg];
                al[mt][2] = *(const uint32_t*)&Al[m + g][k0 + 2 * tg + 8];
                al[mt][3] = *(const uint32_t*)&Al[m + g + 8][k0 + 2 * tg + 8];
            }
#pragma unroll
            for (int nt = 0; nt < 8; nt++) {
                int nn = wn * 64 + nt * 8 + g;
                uint32_t bh[2], bl[2];
                bh[0] = *(const uint32_t*)&Bh[nn][k0 + 2 * tg];
                bh[1] = *(const uint32_t*)&Bh[nn][k0 + 2 * tg + 8];
                bl[0] = *(const uint32_t*)&Bl[nn][k0 + 2 * tg];
                bl[1] = *(const uint32_t*)&Bl[nn][k0 + 2 * tg + 8];
#pragma unroll
                for (int mt = 0; mt < 2; mt++) {
                    mma16816(acc[mt][nt], ah[mt], bh);
                    mma16816(acc[mt][nt], ah[mt], bl);
                    mma16816(acc[mt][nt], al[mt], bh);
                }
            }
        }
        __syncthreads();
    }

    // epilogue: scale by dinv[r], convert to fp16, write half2
#pragma unroll
    for (int mt = 0; mt < 2; mt++) {
        int r0 = brow + wm * 32 + mt * 16 + g;
        int r1 = r0 + 8;
        float s0 = (r0 < M) ? g_dinv[r0] : 0.f;
        float s1 = (r1 < M) ? g_dinv[r1] : 0.f;
#pragma unroll
        for (int nt = 0; nt < 8; nt++) {
            int col = bcol + wn * 64 + nt * 8 + tg * 2;
            if (r0 < M)
                C[(size_t)r0 * 128 + (col >> 1)] =
                    __floats2half2_rn(acc[mt][nt][0] * s0, acc[mt][nt][1] * s0);
            if (r1 < M)
                C[(size_t)r1 * 128 + (col >> 1)] =
                    __floats2half2_rn(acc[mt][nt][2] * s1, acc[mt][nt][3] * s1);
        }
    }
}

// ---------------- aggregation ----------------
__global__ void k_agg(const float2* __restrict__ hws, const float* __restrict__ prev,
                      const float* __restrict__ pscl, const float* __restrict__ psft,
                      const float4* __restrict__ bias, float4* __restrict__ z, int n) {
    int row = blockIdx.x * 4 + (threadIdx.x >> 6);
    if (row >= n) return;
    int lane = threadIdx.x & 63;
    if (lane == 0) g_deg[row] = 0;   // reset for next graph replay (deg unused after preproc)
    int s0 = g_rowptr[row], s1 = g_rowptr[row + 1];

    float4 a0 = make_float4(0.f, 0.f, 0.f, 0.f);
    float4 a1 = make_float4(0.f, 0.f, 0.f, 0.f);
    float4 a2 = make_float4(0.f, 0.f, 0.f, 0.f);
    float4 a3 = make_float4(0.f, 0.f, 0.f, 0.f);

    int e = s0;
    for (; e + 3 < s1; e += 4) {
        int sa = g_csr[e + 0];
        int sb = g_csr[e + 1];
        int sc = g_csr[e + 2];
        int sd = g_csr[e + 3];
        float2 pa = hws[(size_t)sa * 64 + lane];
        float2 pb = hws[(size_t)sb * 64 + lane];
        float2 pc = hws[(size_t)sc * 64 + lane];
        float2 pd = hws[(size_t)sd * 64 + lane];
        float4 va = h4_to_f4(pa);
        float4 vb = h4_to_f4(pb);
        float4 vc = h4_to_f4(pc);
        float4 vd = h4_to_f4(pd);
        a0.x += va.x; a0.y += va.y; a0.z += va.z; a0.w += va.w;
        a1.x += vb.x; a1.y += vb.y; a1.z += vb.z; a1.w += vb.w;
        a2.x += vc.x; a2.y += vc.y; a2.z += vc.z; a2.w += vc.w;
        a3.x += vd.x; a3.y += vd.y; a3.z += vd.z; a3.w += vd.w;
    }
    for (; e < s1; ++e) {
        int sa = g_csr[e];
        float4 va = h4_to_f4(hws[(size_t)sa * 64 + lane]);
        a0.x += va.x; a0.y += va.y; a0.z += va.z; a0.w += va.w;
    }
    a0.x += a1.x + a2.x + a3.x;
    a0.y += a1.y + a2.y + a3.y;
    a0.z += a1.z + a2.z + a3.z;
    a0.w += a1.w + a2.w + a3.w;

    float d = g_dinv[row];
    float4 b = bias[lane];
    float4 o;
    o.x = fmaf(d, a0.x, b.x);
    o.y = fmaf(d, a0.y, b.y);
    o.z = fmaf(d, a0.z, b.z);
    o.w = fmaf(d, a0.w, b.w);
    if (prev) {
        const float4* p4 = (const float4*)prev;
        float4 p = p4[(size_t)row * 64 + lane];
        if (pscl) {
            int c = lane * 4;
            o.x += elu_act(p.x, pscl[c + 0], psft[c + 0]);
            o.y += elu_act(p.y, pscl[c + 1], psft[c + 1]);
            o.z += elu_act(p.z, pscl[c + 2], psft[c + 2]);
            o.w += elu_act(p.w, pscl[c + 3], psft[c + 3]);
        } else {
            o.x += p.x; o.y += p.y; o.z += p.z; o.w += p.w;
        }
    }
    z[(size_t)row * 64 + lane] = o;
}

// ---------------- batchnorm stats ----------------
__global__ void k_stats(const float* __restrict__ z, int n) {
    int t = threadIdx.x;
    int r0 = blockIdx.x * 128;
    int r1 = min(n, r0 + 128);
    float s = 0.f, q = 0.f;
    for (int r = r0; r < r1; ++r) {
        float v = z[(size_t)r * DCOL + t];
        s += v;
        q += v * v;
    }
    atomicAdd(&g_colsum[t], s);
    atomicAdd(&g_colsq[t], q);
}

__global__ void k_bn_finalize(const float* __restrict__ gamma, const float* __restrict__ beta,
                              int n, int layer) {
    int t = threadIdx.x;
    float inv_n = 1.f / (float)n;
    float mu = g_colsum[t] * inv_n;
    float var = g_colsq[t] * inv_n - mu * mu;
    float rs = rsqrtf(var + 1e-5f);
    float sc = gamma[t] * rs;
    g_sc[layer][t] = sc;
    g_sh[layer][t] = beta[t] - mu * sc;
    g_colsum[t] = 0.f;
    g_colsq[t] = 0.f;
}

// ---------------- pool + readout (lazy act on z2) ----------------
__global__ void k_pool_out(const float* __restrict__ z, const int* __restrict__ batch,
                           const float* __restrict__ Wr, const float* __restrict__ br,
                           float* __restrict__ out, int n) {
    int gg = blockIdx.x;
    int t = threadIdx.x;
    int lo = 0, hi = n;
    while (lo < hi) { int m = (lo + hi) >> 1; if (batch[m] < gg) lo = m + 1; else hi = m; }
    int start = lo;
    lo = start; hi = n;
    while (lo < hi) { int m = (lo + hi) >> 1; if (batch[m] < gg + 1) lo = m + 1; else hi = m; }
    int end = lo;

    float sc = g_sc[2][t], sh = g_sh[2][t];
    float sum = 0.f;
    for (int r = start; r < end; ++r)
        sum += elu_act(z[(size_t)r * DCOL + t], sc, sh);
    float cnt = (float)(end - start);
    float v = sum / fmaxf(cnt, 1.f);

    __shared__ float red[DCOL];
    for (int c = 0; c < 2; ++c) {
        red[t] = v * Wr[t * 2 + c];
        __syncthreads();
        for (int s = 128; s > 0; s >>= 1) {
            if (t < s) red[t] += red[t + s];
            __syncthreads();
        }
        if (t == 0) out[gg * 2 + c] = red[0] + br[c];
        __syncthreads();
    }
}

// ---------------- launch ----------------
extern "C" void kernel_launch(void* const* d_in, const int* in_sizes, int n_in,
                              void* d_out, int out_size) {
    const float* x     = (const float*)d_in[0];
    const int*   ei    = (const int*)d_in[1];
    const int*   batch = (const int*)d_in[2];
    const float* W[3]     = { (const float*)d_in[3],  (const float*)d_in[7],  (const float*)d_in[11] };
    const float* b[3]     = { (const float*)d_in[4],  (const float*)d_in[8],  (const float*)d_in[12] };
    const float* gamma[3] = { (const float*)d_in[5],  (const float*)d_in[9],  (const float*)d_in[13] };
    const float* beta[3]  = { (const float*)d_in[6],  (const float*)d_in[10], (const float*)d_in[14] };
    const float* Wr = (const float*)d_in[15];
    const float* br = (const float*)d_in[16];
    float* out = (float*)d_out;

    int n = in_sizes[0] / DCOL;
    int e = in_sizes[1] / 2;
    int g = out_size / 2;
    const int* src = ei;
    const int* dst = ei + e;

    __half2* p_hw;
    float *p_z0, *p_z1, *p_sc, *p_sh;
    __half *p_whi, *p_wlo;
    cudaGetSymbolAddress((void**)&p_hw, g_hw);
    cudaGetSymbolAddress((void**)&p_z0, g_h1);
    cudaGetSymbolAddress((void**)&p_z1, g_h2);
    cudaGetSymbolAddress((void**)&p_sc, g_sc);
    cudaGetSymbolAddress((void**)&p_sh, g_sh);
    cudaGetSymbolAddress((void**)&p_whi, g_Whi);
    cudaGetSymbolAddress((void**)&p_wlo, g_Wlo);

    // ---- preprocessing: exactly 5 launches, so launch #6 (first k_gemm) is the ncu target ----
    int nb256_e = (e + 255) / 256;
    int nb1024  = (n + 1023) / 1024;
    int nb_fill = (e + n + 255) / 256;

    k_count_deg<<<nb256_e, 256>>>(dst, e);                         // 1
    k_scan_block<<<nb1024, 1024>>>(n);                             // 2
    k_scan_sums_prepW<<<1 + 768, 256>>>(nb1024, W[0], W[1], W[2]); // 3
    k_scan_final<<<nb1024, 1024>>>(n);                             // 4
    k_fill<<<nb_fill, 256>>>(src, dst, e, n);                      // 5

    dim3 gemm_grid((n + 127) / 128, 2);
    int nb_agg   = (n + 3) / 4;
    int nb_stats = (n + 127) / 128;

    // ---- layer 0: A=x raw, prev=none -> z0 ----
    k_gemm<<<gemm_grid, 256>>>(x, p_whi + 0 * 65536, p_wlo + 0 * 65536, p_hw, n, nullptr, nullptr);
    k_agg<<<nb_agg, 256>>>((const float2*)p_hw, nullptr, nullptr, nullptr,
                           (const float4*)b[0], (float4*)p_z0, n);
    k_stats<<<nb_stats, 256>>>(p_z0, n);
    k_bn_finalize<<<1, 256>>>(gamma[0], beta[0], n, 0);

    // ---- layer 1: A=act0(z0), prev=x raw -> z1 ----
    k_gemm<<<gemm_grid, 256>>>(p_z0, p_whi + 1 * 65536, p_wlo + 1 * 65536, p_hw, n,
                               p_sc + 0 * DCOL, p_sh + 0 * DCOL);
    k_agg<<<nb_agg, 256>>>((const float2*)p_hw, x, nullptr, nullptr,
                           (const float4*)b[1], (float4*)p_z1, n);
    k_stats<<<nb_stats, 256>>>(p_z1, n);
    k_bn_finalize<<<1, 256>>>(gamma[1], beta[1], n, 1);

    // ---- layer 2: A=act1(z1), prev=act0(z0) -> z2 (overwrites z0, elementwise safe) ----
    k_gemm<<<gemm_grid, 256>>>(p_z1, p_whi + 2 * 65536, p_wlo + 2 * 65536, p_hw, n,
                               p_sc + 1 * DCOL, p_sh + 1 * DCOL);
    k_agg<<<nb_agg, 256>>>((const float2*)p_hw, p_z0, p_sc + 0 * DCOL, p_sh + 0 * DCOL,
                           (const float4*)b[2], (float4*)p_z0, n);
    k_stats<<<nb_stats, 256>>>(p_z0, n);
    k_bn_finalize<<<1, 256>>>(gamma[2], beta[2], n, 2);

    // ---- pool + readout (act2 lazy) ----
    k_pool_out<<<g, 256>>>(p_z0, batch, Wr, br, out, n);
}

// round 7
// speedup vs baseline: 1.8113x; 1.0458x over previous
#include <cuda_runtime.h>
#include <cuda_fp16.h>
#include <cstdint>
#include <math.h>

#define MAXN 65536
#define MAXE (1 << 21)
#define DCOL 256

// ---------------- static device scratch ----------------
__device__ __half2 g_hw[MAXN * (DCOL / 2)];  // (h @ W) * dinv[row], fp16
__device__ float g_h1[MAXN * DCOL];   // z0 / z2
__device__ float g_h2[MAXN * DCOL];   // z1
__device__ int   g_deg[MAXN];         // starts 0; re-zeroed by k_agg each call
__device__ int   g_scan[MAXN];
__device__ int   g_rowptr[MAXN + 1];
__device__ int   g_cursor[MAXN];
__device__ int   g_csr[MAXE];
__device__ int   g_bsums[128];
__device__ float g_dinv[MAXN];
__device__ float g_colsum[DCOL];
__device__ float g_colsq[DCOL];
__device__ float g_sc[3][DCOL];
__device__ float g_sh[3][DCOL];
__device__ __half g_Whi[3][DCOL * DCOL];  // W split hi, transposed [n][k]
__device__ __half g_Wlo[3][DCOL * DCOL];  // W split lo, transposed [n][k]

__device__ __forceinline__ float elu_act(float z, float sc, float sh) {
    float v = fmaf(z, sc, sh);
    return v > 0.f ? v : expm1f(v);
}

__device__ __forceinline__ void mma16816(float* d, const uint32_t* a, const uint32_t* b) {
    asm volatile(
        "mma.sync.aligned.m16n8k16.row.col.f32.f16.f16.f32 "
        "{%0,%1,%2,%3},{%4,%5,%6,%7},{%8,%9},{%0,%1,%2,%3};"
        : "+f"(d[0]), "+f"(d[1]), "+f"(d[2]), "+f"(d[3])
        : "r"(a[0]), "r"(a[1]), "r"(a[2]), "r"(a[3]), "r"(b[0]), "r"(b[1]));
}

__device__ __forceinline__ void ldsm_x4(uint32_t* r, uint32_t saddr) {
    asm volatile("ldmatrix.sync.aligned.m8n8.x4.shared.b16 {%0,%1,%2,%3}, [%4];"
                 : "=r"(r[0]), "=r"(r[1]), "=r"(r[2]), "=r"(r[3]) : "r"(saddr));
}

__device__ __forceinline__ void cp_async16(uint32_t saddr, const void* gptr) {
    asm volatile("cp.async.cg.shared.global [%0], [%1], 16;" :: "r"(saddr), "l"(gptr));
}

// unpack 4 halves (as float2 bits) into float4
__device__ __forceinline__ float4 h4_to_f4(float2 p) {
    __half2 h0 = *reinterpret_cast<__half2*>(&p.x);
    __half2 h1 = *reinterpret_cast<__half2*>(&p.y);
    float2 a = __half22float2(h0);
    float2 b = __half22float2(h1);
    return make_float4(a.x, a.y, b.x, b.y);
}

// ---------------- preprocessing (5 launches) ----------------
__global__ void k_count_deg(const int* __restrict__ dst, int e) {
    int i = blockIdx.x * blockDim.x + threadIdx.x;
    if (i < e) atomicAdd(&g_deg[dst[i]], 1);
}

__global__ void k_scan_block(int n) {
    __shared__ int sh[1024];
    int i = blockIdx.x * 1024 + threadIdx.x;
    int v = 0;
    if (i < n) {
        v = g_deg[i] + 1;          // + self loop
        g_deg[i] = v;
        g_dinv[i] = rsqrtf((float)v);
    }
    sh[threadIdx.x] = v;
    __syncthreads();
    for (int off = 1; off < 1024; off <<= 1) {
        int t = (threadIdx.x >= off) ? sh[threadIdx.x - off] : 0;
        __syncthreads();
        sh[threadIdx.x] += t;
        __syncthreads();
    }
    if (i < n) g_scan[i] = sh[threadIdx.x];
    if (threadIdx.x == 1023) g_bsums[blockIdx.x] = sh[1023];
}

__global__ void k_scan_sums_prepW(int nb, const float* __restrict__ W0,
                                  const float* __restrict__ W1, const float* __restrict__ W2) {
    if (blockIdx.x == 0) {
        if (threadIdx.x == 0) {
            int acc = 0;
            for (int i = 0; i < nb; i++) { acc += g_bsums[i]; g_bsums[i] = acc; }
        }
        return;
    }
    int idx = (blockIdx.x - 1) * 256 + threadIdx.x;   // 0 .. 3*65536-1
    int layer = idx >> 16;
    int rem = idx & 65535;           // rem = k*256 + n
    int k = rem >> 8;
    int nn = rem & 255;
    const float* Ws = (layer == 0) ? W0 : (layer == 1) ? W1 : W2;
    float w = Ws[rem];
    __half hi = __float2half_rn(w);
    __half lo = __float2half_rn(w - __half2float(hi));
    g_Whi[layer][nn * 256 + k] = hi;
    g_Wlo[layer][nn * 256 + k] = lo;
}

__global__ void k_scan_final(int n) {
    int i = blockIdx.x * 1024 + threadIdx.x;
    if (i < n) {
        int off = (blockIdx.x > 0) ? g_bsums[blockIdx.x - 1] : 0;
        int incl = g_scan[i] + off;
        g_rowptr[i + 1] = incl;
        g_cursor[i] = incl - g_deg[i];
        if (i == 0) g_rowptr[0] = 0;
    }
}

__global__ void k_fill(const int* __restrict__ src, const int* __restrict__ dst, int e, int n) {
    int i = blockIdx.x * blockDim.x + threadIdx.x;
    if (i < e) {
        int d = dst[i];
        int p = atomicAdd(&g_cursor[d], 1);
        g_csr[p] = src[i];
    } else if (i - e < n) {
        int j = i - e;
        int p = atomicAdd(&g_cursor[j], 1);
        g_csr[p] = j;
    }
}

// ---------------- pipelined fp16x2-split tensor-core GEMM ----------------
// Chw[r][c] = fp16( (act(A) @ W)[r][c] * dinv[r] ), A: Mx256 fp32 row-major.
// Whi/Wlo pre-split fp16, transposed [n][k]. 3-term mma: hi*hi + hi*lo + lo*hi.
// BM=64, BN=256 (full), BK=32, 256 threads = 8 warps (2m x 4n), warp tile 32x64.
// Double-buffered: cp.async for B, reg-staged LDG+convert for A; ldmatrix frags.
#define PADK 40
__global__ __launch_bounds__(256, 2)
void k_gemm(const float* __restrict__ A,
            const __half* __restrict__ Whi, const __half* __restrict__ Wlo,
            __half2* __restrict__ C, int M,
            const float* __restrict__ scl, const float* __restrict__ sft) {
    extern __shared__ __half sm[];
    __half* Ah = sm;                              // 2 stages * 64 * PADK
    __half* Al = Ah + 2 * 64 * PADK;
    __half* Bh = Al + 2 * 64 * PADK;              // 2 stages * 256 * PADK
    __half* Bl = Bh + 2 * 256 * PADK;

    uint32_t sAh = (uint32_t)__cvta_generic_to_shared(Ah);
    uint32_t sAl = (uint32_t)__cvta_generic_to_shared(Al);
    uint32_t sBh = (uint32_t)__cvta_generic_to_shared(Bh);
    uint32_t sBl = (uint32_t)__cvta_generic_to_shared(Bl);

    int tid = threadIdx.x;
    int brow = blockIdx.x * 64;
    int lane = tid & 31;
    int warp = tid >> 5;
    int wm = warp & 1;        // 0..1 -> rows wm*32
    int wn = warp >> 1;       // 0..3 -> cols wn*64
    int g  = lane >> 2;
    int tg = lane & 3;

    // A loader mapping: row 0..63, col base {0,8,16,24}
    int aRow = tid >> 2;
    int aCb  = (tid & 3) * 8;
    int gRow = brow + aRow;
    const float* Aptr = A + (size_t)gRow * 256 + aCb;

    // B cp.async mapping: rows (tid>>2)+rep*64, 16B chunk (tid&3)*8 halves
    int bRow0 = tid >> 2;
    int bChunk = (tid & 3) * 8;

    // ldmatrix lane mapping (shared by A and B frags)
    int lmRow = lane & 15;
    int lmCol = (lane >> 4) * 8;

    float acc[2][8][4];
#pragma unroll
    for (int mt = 0; mt < 2; mt++)
#pragma unroll
        for (int nt = 0; nt < 8; nt++)
#pragma unroll
            for (int j = 0; j < 4; j++) acc[mt][nt][j] = 0.f;

    // ---------- helpers as lambdas ----------
    auto loadA = [&](int kt, float4& v0, float4& v1) {
        if (gRow < M) {
            v0 = *(const float4*)(Aptr + kt);
            v1 = *(const float4*)(Aptr + kt + 4);
        } else {
            v0 = make_float4(0.f, 0.f, 0.f, 0.f);
            v1 = make_float4(0.f, 0.f, 0.f, 0.f);
        }
        if (scl) {
            int c = kt + aCb;
            v0.x = elu_act(v0.x, scl[c + 0], sft[c + 0]);
            v0.y = elu_act(v0.y, scl[c + 1], sft[c + 1]);
            v0.z = elu_act(v0.z, scl[c + 2], sft[c + 2]);
            v0.w = elu_act(v0.w, scl[c + 3], sft[c + 3]);
            v1.x = elu_act(v1.x, scl[c + 4], sft[c + 4]);
            v1.y = elu_act(v1.y, scl[c + 5], sft[c + 5]);
            v1.z = elu_act(v1.z, scl[c + 6], sft[c + 6]);
            v1.w = elu_act(v1.w, scl[c + 7], sft[c + 7]);
        }
    };
    auto storeA = [&](int stage, float4 v0, float4 v1) {
        __half* ah = Ah + stage * 64 * PADK + aRow * PADK + aCb;
        __half* al = Al + stage * 64 * PADK + aRow * PADK + aCb;
        float f[8] = {v0.x, v0.y, v0.z, v0.w, v1.x, v1.y, v1.z, v1.w};
        __half hi[8], lo[8];
#pragma unroll
        for (int j = 0; j < 8; j++) {
            hi[j] = __float2half_rn(f[j]);
            lo[j] = __float2half_rn(f[j] - __half2float(hi[j]));
        }
#pragma unroll
        for (int j = 0; j < 4; j++) {
            *(__half2*)(ah + 2 * j) = __halves2half2(hi[2 * j], hi[2 * j + 1]);
            *(__half2*)(al + 2 * j) = __halves2half2(lo[2 * j], lo[2 * j + 1]);
        }
    };
    auto asyncB = [&](int stage, int kt) {
#pragma unroll
        for (int rep = 0; rep < 4; rep++) {
            int row = bRow0 + rep * 64;
            uint32_t soff = (uint32_t)((stage * 256 + row) * PADK + bChunk) * 2;
            const __half* gh = Whi + (size_t)row * 256 + kt + bChunk;
            const __half* gl = Wlo + (size_t)row * 256 + kt + bChunk;
            cp_async16(sBh + soff, gh);
            cp_async16(sBl + soff, gl);
        }
    };
    auto compute = [&](int stage) {
#pragma unroll
        for (int ks = 0; ks < 2; ks++) {
            int k0 = ks * 16;
            uint32_t ah[2][4], al[2][4];
#pragma unroll
            for (int mt = 0; mt < 2; mt++) {
                int m = wm * 32 + mt * 16 + lmRow;
                uint32_t off = (uint32_t)((stage * 64 + m) * PADK + k0 + lmCol) * 2;
                ldsm_x4(ah[mt], sAh + off);
                ldsm_x4(al[mt], sAl + off);
            }
#pragma unroll
            for (int pair = 0; pair < 4; pair++) {
                int n0 = wn * 64 + pair * 16 + lmRow;
                uint32_t off = (uint32_t)((stage * 256 + n0) * PADK + k0 + lmCol) * 2;
                uint32_t bhr[4], blr[4];
                ldsm_x4(bhr, sBh + off);
                ldsm_x4(blr, sBl + off);
                uint32_t b_ev_h[2] = {bhr[0], bhr[2]};
                uint32_t b_od_h[2] = {bhr[1], bhr[3]};
                uint32_t b_ev_l[2] = {blr[0], blr[2]};
                uint32_t b_od_l[2] = {blr[1], blr[3]};
                int nt0 = pair * 2;
#pragma unroll
                for (int mt = 0; mt < 2; mt++) {
                    mma16816(acc[mt][nt0], ah[mt], b_ev_h);
                    mma16816(acc[mt][nt0], ah[mt], b_ev_l);
                    mma16816(acc[mt][nt0], al[mt], b_ev_h);
                    mma16816(acc[mt][nt0 + 1], ah[mt], b_od_h);
                    mma16816(acc[mt][nt0 + 1], ah[mt], b_od_l);
                    mma16816(acc[mt][nt0 + 1], al[mt], b_od_h);
                }
            }
        }
    };

    // ---------- prologue: fill stage 0 ----------
    {
        asyncB(0, 0);
        float4 v0, v1;
        loadA(0, v0, v1);
        storeA(0, v0, v1);
        asm volatile("cp.async.commit_group;");
        asm volatile("cp.async.wait_group 0;");
        __syncthreads();
    }

    // ---------- main loop: 8 K-tiles ----------
#pragma unroll
    for (int it = 0; it < 8; ++it) {
        int cur = it & 1;
        float4 v0, v1;
        if (it < 7) {
            asyncB(cur ^ 1, (it + 1) * 32);
            loadA((it + 1) * 32, v0, v1);
        }
        asm volatile("cp.async.commit_group;");
        compute(cur);
        if (it < 7) storeA(cur ^ 1, v0, v1);
        asm volatile("cp.async.wait_group 0;");
        __syncthreads();
    }

    // ---------- epilogue: dinv scale, fp16 store ----------
#pragma unroll
    for (int mt = 0; mt < 2; mt++) {
        int r0 = brow + wm * 32 + mt * 16 + g;
        int r1 = r0 + 8;
        float s0 = (r0 < M) ? g_dinv[r0] : 0.f;
        float s1 = (r1 < M) ? g_dinv[r1] : 0.f;
#pragma unroll
        for (int nt = 0; nt < 8; nt++) {
            int col = wn * 64 + nt * 8 + tg * 2;
            if (r0 < M)
                C[(size_t)r0 * 128 + (col >> 1)] =
                    __floats2half2_rn(acc[mt][nt][0] * s0, acc[mt][nt][1] * s0);
            if (r1 < M)
                C[(size_t)r1 * 128 + (col >> 1)] =
                    __floats2half2_rn(acc[mt][nt][2] * s1, acc[mt][nt][3] * s1);
        }
    }
}

// ---------------- aggregation ----------------
__global__ void k_agg(const float2* __restrict__ hws, const float* __restrict__ prev,
                      const float* __restrict__ pscl, const float* __restrict__ psft,
                      const float4* __restrict__ bias, float4* __restrict__ z, int n) {
    int row = blockIdx.x * 4 + (threadIdx.x >> 6);
    if (row >= n) return;
    int lane = threadIdx.x & 63;
    if (lane == 0) g_deg[row] = 0;   // reset for next graph replay
    int s0 = g_rowptr[row], s1 = g_rowptr[row + 1];

    float4 a0 = make_float4(0.f, 0.f, 0.f, 0.f);
    float4 a1 = make_float4(0.f, 0.f, 0.f, 0.f);
    float4 a2 = make_float4(0.f, 0.f, 0.f, 0.f);
    float4 a3 = make_float4(0.f, 0.f, 0.f, 0.f);

    int e = s0;
    for (; e + 3 < s1; e += 4) {
        int sa = g_csr[e + 0];
        int sb = g_csr[e + 1];
        int sc = g_csr[e + 2];
        int sd = g_csr[e + 3];
        float2 pa = hws[(size_t)sa * 64 + lane];
        float2 pb = hws[(size_t)sb * 64 + lane];
        float2 pc = hws[(size_t)sc * 64 + lane];
        float2 pd = hws[(size_t)sd * 64 + lane];
        float4 va = h4_to_f4(pa);
        float4 vb = h4_to_f4(pb);
        float4 vc = h4_to_f4(pc);
        float4 vd = h4_to_f4(pd);
        a0.x += va.x; a0.y += va.y; a0.z += va.z; a0.w += va.w;
        a1.x += vb.x; a1.y += vb.y; a1.z += vb.z; a1.w += vb.w;
        a2.x += vc.x; a2.y += vc.y; a2.z += vc.z; a2.w += vc.w;
        a3.x += vd.x; a3.y += vd.y; a3.z += vd.z; a3.w += vd.w;
    }
    for (; e < s1; ++e) {
        int sa = g_csr[e];
        float4 va = h4_to_f4(hws[(size_t)sa * 64 + lane]);
        a0.x += va.x; a0.y += va.y; a0.z += va.z; a0.w += va.w;
    }
    a0.x += a1.x + a2.x + a3.x;
    a0.y += a1.y + a2.y + a3.y;
    a0.z += a1.z + a2.z + a3.z;
    a0.w += a1.w + a2.w + a3.w;

    float d = g_dinv[row];
    float4 b = bias[lane];
    float4 o;
    o.x = fmaf(d, a0.x, b.x);
    o.y = fmaf(d, a0.y, b.y);
    o.z = fmaf(d, a0.z, b.z);
    o.w = fmaf(d, a0.w, b.w);
    if (prev) {
        const float4* p4 = (const float4*)prev;
        float4 p = p4[(size_t)row * 64 + lane];
        if (pscl) {
            int c = lane * 4;
            o.x += elu_act(p.x, pscl[c + 0], psft[c + 0]);
            o.y += elu_act(p.y, pscl[c + 1], psft[c + 1]);
            o.z += elu_act(p.z, pscl[c + 2], psft[c + 2]);
            o.w += elu_act(p.w, pscl[c + 3], psft[c + 3]);
        } else {
            o.x += p.x; o.y += p.y; o.z += p.z; o.w += p.w;
        }
    }
    z[(size_t)row * 64 + lane] = o;
}

// ---------------- batchnorm stats ----------------
__global__ void k_stats(const float* __restrict__ z, int n) {
    int t = threadIdx.x;
    int r0 = blockIdx.x * 128;
    int r1 = min(n, r0 + 128);
    float s = 0.f, q = 0.f;
    for (int r = r0; r < r1; ++r) {
        float v = z[(size_t)r * DCOL + t];
        s += v;
        q += v * v;
    }
    atomicAdd(&g_colsum[t], s);
    atomicAdd(&g_colsq[t], q);
}

__global__ void k_bn_finalize(const float* __restrict__ gamma, const float* __restrict__ beta,
                              int n, int layer) {
    int t = threadIdx.x;
    float inv_n = 1.f / (float)n;
    float mu = g_colsum[t] * inv_n;
    float var = g_colsq[t] * inv_n - mu * mu;
    float rs = rsqrtf(var + 1e-5f);
    float sc = gamma[t] * rs;
    g_sc[layer][t] = sc;
    g_sh[layer][t] = beta[t] - mu * sc;
    g_colsum[t] = 0.f;
    g_colsq[t] = 0.f;
}

// ---------------- pool + readout (lazy act on z2) ----------------
__global__ void k_pool_out(const float* __restrict__ z, const int* __restrict__ batch,
                           const float* __restrict__ Wr, const float* __restrict__ br,
                           float* __restrict__ out, int n) {
    int gg = blockIdx.x;
    int t = threadIdx.x;
    int lo = 0, hi = n;
    while (lo < hi) { int m = (lo + hi) >> 1; if (batch[m] < gg) lo = m + 1; else hi = m; }
    int start = lo;
    lo = start; hi = n;
    while (lo < hi) { int m = (lo + hi) >> 1; if (batch[m] < gg + 1) lo = m + 1; else hi = m; }
    int end = lo;

    float sc = g_sc[2][t], sh = g_sh[2][t];
    float sum = 0.f;
    for (int r = start; r < end; ++r)
        sum += elu_act(z[(size_t)r * DCOL + t], sc, sh);
    float cnt = (float)(end - start);
    float v = sum / fmaxf(cnt, 1.f);

    __shared__ float red[DCOL];
    for (int c = 0; c < 2; ++c) {
        red[t] = v * Wr[t * 2 + c];
        __syncthreads();
        for (int s = 128; s > 0; s >>= 1) {
            if (t < s) red[t] += red[t + s];
            __syncthreads();
        }
        if (t == 0) out[gg * 2 + c] = red[0] + br[c];
        __syncthreads();
    }
}

// ---------------- launch ----------------
extern "C" void kernel_launch(void* const* d_in, const int* in_sizes, int n_in,
                              void* d_out, int out_size) {
    const float* x     = (const float*)d_in[0];
    const int*   ei    = (const int*)d_in[1];
    const int*   batch = (const int*)d_in[2];
    const float* W[3]     = { (const float*)d_in[3],  (const float*)d_in[7],  (const float*)d_in[11] };
    const float* b[3]     = { (const float*)d_in[4],  (const float*)d_in[8],  (const float*)d_in[12] };
    const float* gamma[3] = { (const float*)d_in[5],  (const float*)d_in[9],  (const float*)d_in[13] };
    const float* beta[3]  = { (const float*)d_in[6],  (const float*)d_in[10], (const float*)d_in[14] };
    const float* Wr = (const float*)d_in[15];
    const float* br = (const float*)d_in[16];
    float* out = (float*)d_out;

    int n = in_sizes[0] / DCOL;
    int e = in_sizes[1] / 2;
    int g = out_size / 2;
    const int* src = ei;
    const int* dst = ei + e;

    __half2* p_hw;
    float *p_z0, *p_z1, *p_sc, *p_sh;
    __half *p_whi, *p_wlo;
    cudaGetSymbolAddress((void**)&p_hw, g_hw);
    cudaGetSymbolAddress((void**)&p_z0, g_h1);
    cudaGetSymbolAddress((void**)&p_z1, g_h2);
    cudaGetSymbolAddress((void**)&p_sc, g_sc);
    cudaGetSymbolAddress((void**)&p_sh, g_sh);
    cudaGetSymbolAddress((void**)&p_whi, g_Whi);
    cudaGetSymbolAddress((void**)&p_wlo, g_Wlo);

    const int GEMM_SMEM = (2 * 64 * PADK + 2 * 64 * PADK + 2 * 256 * PADK + 2 * 256 * PADK) * 2;
    cudaFuncSetAttribute(k_gemm, cudaFuncAttributeMaxDynamicSharedMemorySize, GEMM_SMEM);

    // ---- preprocessing: 5 launches ----
    int nb256_e = (e + 255) / 256;
    int nb1024  = (n + 1023) / 1024;
    int nb_fill = (e + n + 255) / 256;

    k_count_deg<<<nb256_e, 256>>>(dst, e);
    k_scan_block<<<nb1024, 1024>>>(n);
    k_scan_sums_prepW<<<1 + 768, 256>>>(nb1024, W[0], W[1], W[2]);
    k_scan_final<<<nb1024, 1024>>>(n);
    k_fill<<<nb_fill, 256>>>(src, dst, e, n);

    int gemm_grid = (n + 63) / 64;
    int nb_agg   = (n + 3) / 4;
    int nb_stats = (n + 127) / 128;

    // ---- layer 0: A=x raw, prev=none -> z0 ----
    k_gemm<<<gemm_grid, 256, GEMM_SMEM>>>(x, p_whi + 0 * 65536, p_wlo + 0 * 65536, p_hw, n, nullptr, nullptr);
    k_agg<<<nb_agg, 256>>>((const float2*)p_hw, nullptr, nullptr, nullptr,
                           (const float4*)b[0], (float4*)p_z0, n);
    k_stats<<<nb_stats, 256>>>(p_z0, n);
    k_bn_finalize<<<1, 256>>>(gamma[0], beta[0], n, 0);

    // ---- layer 1: A=act0(z0), prev=x raw -> z1 ----
    k_gemm<<<gemm_grid, 256, GEMM_SMEM>>>(p_z0, p_whi + 1 * 65536, p_wlo + 1 * 65536, p_hw, n,
                                          p_sc + 0 * DCOL, p_sh + 0 * DCOL);
    k_agg<<<nb_agg, 256>>>((const float2*)p_hw, x, nullptr, nullptr,
                           (const float4*)b[1], (float4*)p_z1, n);
    k_stats<<<nb_stats, 256>>>(p_z1, n);
    k_bn_finalize<<<1, 256>>>(gamma[1], beta[1], n, 1);

    // ---- layer 2: A=act1(z1), prev=act0(z0) -> z2 (overwrites z0, elementwise safe) ----
    k_gemm<<<gemm_grid, 256, GEMM_SMEM>>>(p_z1, p_whi + 2 * 65536, p_wlo + 2 * 65536, p_hw, n,
                                          p_sc + 1 * DCOL, p_sh + 1 * DCOL);
    k_agg<<<nb_agg, 256>>>((const float2*)p_hw, p_z0, p_sc + 0 * DCOL, p_sh + 0 * DCOL,
                           (const float4*)b[2], (float4*)p_z0, n);
    k_stats<<<nb_stats, 256>>>(p_z0, n);
    k_bn_finalize<<<1, 256>>>(gamma[2], beta[2], n, 2);

    // ---- pool + readout (act2 lazy) ----
    k_pool_out<<<g, 256>>>(p_z0, batch, Wr, br, out, n);
}